// round 3
// baseline (speedup 1.0000x reference)
#include <cuda_runtime.h>
#include <math.h>
#include <stdint.h>

// Problem constants
#define Sdim  2048
#define Hdim  4096
#define NHEAD 32
#define HDIM  128
#define QKVN  12288   // 3*Hdim

// Scratch (allocation-free rule: __device__ globals)
__device__ float g_qkv[(size_t)Sdim * QKVN];   // ~100.7 MB
__device__ float g_ctx[(size_t)Sdim * Hdim];   // ~33.6 MB

__device__ __forceinline__ unsigned f2tf32(float x) {
    unsigned u;
    asm("cvt.rna.tf32.f32 %0, %1;" : "=r"(u) : "f"(x));
    return u;
}

// ---------------------------------------------------------------------------
// TF32 tensor-core GEMM:  C[M,N] = A[M,K] @ B[N,K]^T + bias[N]
// A row-major (K contiguous), B row-major (N,K) -> natural TN layout for
// mma.sync.m16n8k8.row.col. CTA tile 128x128x32, 8 warps (2x4), warp 64x32.
// ---------------------------------------------------------------------------
#define BM 128
#define BN 128
#define BK 32
#define KSTR 36   // padded smem k-stride (words): conflict-free frag reads

__global__ __launch_bounds__(256, 1) void gemm_tf32(
    const float* __restrict__ A, const float* __restrict__ B,
    const float* __restrict__ bias, float* __restrict__ C,
    int M, int N, int K)
{
    __shared__ unsigned As[BM * KSTR];  // 18 KB
    __shared__ unsigned Bs[BN * KSTR];  // 18 KB

    const int tid  = threadIdx.x;
    const int warp = tid >> 5;
    const int lane = tid & 31;
    const int wm = warp >> 2;       // 0..1  (M dir)
    const int wn = warp & 3;        // 0..3  (N dir)
    const int g  = lane >> 2;       // groupID 0..7
    const int tg = lane & 3;        // thread-in-group 0..3
    const int bm = blockIdx.y * BM;
    const int bn = blockIdx.x * BN;

    const int lr = tid >> 3;        // staging row 0..31 (+32*i)
    const int lc = tid & 7;         // staging col4 0..7

    float acc[4][4][4];
#pragma unroll
    for (int i = 0; i < 4; ++i)
#pragma unroll
        for (int j = 0; j < 4; ++j)
#pragma unroll
            for (int c = 0; c < 4; ++c) acc[i][j][c] = 0.f;

    float4 ra[4], rb[4];

#define LOAD_TILES(k0)                                                          \
    {                                                                           \
        _Pragma("unroll")                                                       \
        for (int i = 0; i < 4; ++i) {                                           \
            ra[i] = *reinterpret_cast<const float4*>(                           \
                &A[(size_t)(bm + lr + 32 * i) * K + (k0) + lc * 4]);            \
            rb[i] = *reinterpret_cast<const float4*>(                           \
                &B[(size_t)(bn + lr + 32 * i) * K + (k0) + lc * 4]);            \
        }                                                                       \
    }

#define STORE_TILES()                                                           \
    {                                                                           \
        _Pragma("unroll")                                                       \
        for (int i = 0; i < 4; ++i) {                                           \
            unsigned* pa = &As[(lr + 32 * i) * KSTR + lc * 4];                  \
            pa[0] = f2tf32(ra[i].x); pa[1] = f2tf32(ra[i].y);                   \
            pa[2] = f2tf32(ra[i].z); pa[3] = f2tf32(ra[i].w);                   \
            unsigned* pb = &Bs[(lr + 32 * i) * KSTR + lc * 4];                  \
            pb[0] = f2tf32(rb[i].x); pb[1] = f2tf32(rb[i].y);                   \
            pb[2] = f2tf32(rb[i].z); pb[3] = f2tf32(rb[i].w);                   \
        }                                                                       \
    }

    LOAD_TILES(0);
    STORE_TILES();
    __syncthreads();

    const int nIter = K / BK;
    for (int it = 0; it < nIter; ++it) {
        const bool hasNext = (it + 1 < nIter);
        if (hasNext) LOAD_TILES((it + 1) * BK);

#pragma unroll
        for (int ks = 0; ks < 4; ++ks) {
            unsigned af[4][4], bf[4][2];
#pragma unroll
            for (int i = 0; i < 4; ++i) {
                const int r = wm * 64 + i * 16 + g;
                af[i][0] = As[r * KSTR + ks * 8 + tg];
                af[i][1] = As[(r + 8) * KSTR + ks * 8 + tg];
                af[i][2] = As[r * KSTR + ks * 8 + tg + 4];
                af[i][3] = As[(r + 8) * KSTR + ks * 8 + tg + 4];
            }
#pragma unroll
            for (int j = 0; j < 4; ++j) {
                const int rn = wn * 32 + j * 8 + g;
                bf[j][0] = Bs[rn * KSTR + ks * 8 + tg];
                bf[j][1] = Bs[rn * KSTR + ks * 8 + tg + 4];
            }
#pragma unroll
            for (int i = 0; i < 4; ++i)
#pragma unroll
                for (int j = 0; j < 4; ++j) {
                    asm volatile(
                        "mma.sync.aligned.m16n8k8.row.col.f32.tf32.tf32.f32 "
                        "{%0,%1,%2,%3}, {%4,%5,%6,%7}, {%8,%9}, {%0,%1,%2,%3};\n"
                        : "+f"(acc[i][j][0]), "+f"(acc[i][j][1]),
                          "+f"(acc[i][j][2]), "+f"(acc[i][j][3])
                        : "r"(af[i][0]), "r"(af[i][1]), "r"(af[i][2]), "r"(af[i][3]),
                          "r"(bf[j][0]), "r"(bf[j][1]));
                }
        }
        __syncthreads();
        if (hasNext) {
            STORE_TILES();
            __syncthreads();
        }
    }

    // Epilogue: c0:(g,2tg) c1:(g,2tg+1) c2:(g+8,2tg) c3:(g+8,2tg+1)
#pragma unroll
    for (int i = 0; i < 4; ++i) {
        const int row = bm + wm * 64 + i * 16 + g;
#pragma unroll
        for (int j = 0; j < 4; ++j) {
            const int col = bn + wn * 32 + j * 8 + tg * 2;
            const float b0 = bias[col], b1 = bias[col + 1];
            C[(size_t)row * N + col]           = acc[i][j][0] + b0;
            C[(size_t)row * N + col + 1]       = acc[i][j][1] + b1;
            C[(size_t)(row + 8) * N + col]     = acc[i][j][2] + b0;
            C[(size_t)(row + 8) * N + col + 1] = acc[i][j][3] + b1;
        }
    }
#undef LOAD_TILES
#undef STORE_TILES
}

// ---------------------------------------------------------------------------
// Partial RoPE (first 32 dims of q and k). One thread per (s, head, pair).
// Double-precision phase/sincos: well within 1e-3 of the fp32 reference.
// ---------------------------------------------------------------------------
__global__ void rope_kernel(float* __restrict__ qkv) {
    const int idx = blockIdx.x * blockDim.x + threadIdx.x;
    if (idx >= Sdim * NHEAD * 16) return;
    const int i = idx & 15;          // pair index 0..15
    const int h = (idx >> 4) & 31;
    const int s = idx >> 9;

    const double invf = pow(10000.0, -((double)(2 * i) / 32.0));
    double sd, cd;
    sincos((double)s * invf, &sd, &cd);
    const float c = (float)cd, sn = (float)sd;

    float* base = qkv + (size_t)s * QKVN + h * 384;
    // q
    {
        const float x0 = base[i], x1 = base[i + 16];
        base[i]      = x0 * c - x1 * sn;
        base[i + 16] = x1 * c + x0 * sn;
    }
    // k (offset +128)
    {
        const float x0 = base[128 + i], x1 = base[128 + i + 16];
        base[128 + i]      = x0 * c - x1 * sn;
        base[128 + i + 16] = x1 * c + x0 * sn;
    }
}

// ---------------------------------------------------------------------------
// Causal flash attention, fp32 scalar. CTA = (64 q-rows, one head).
// 256 threads: 4 lanes per row; lane l4 owns dims {16j + 4*l4 .. +3}.
// K/V tiles (64x128 each) in dynamic smem; LDS.128 reads are broadcast /
// conflict-free by construction. Online softmax in 16-score chunks.
// ---------------------------------------------------------------------------
#define QT 64
#define KT 64

__global__ __launch_bounds__(256) void flash_attn(
    const float* __restrict__ qkv, float* __restrict__ ctx)
{
    extern __shared__ float sh[];
    float* Ks = sh;                 // [KT][128]
    float* Vs = sh + KT * HDIM;     // [KT][128]

    const int h   = blockIdx.y;
    const int qb  = blockIdx.x;
    const int tid = threadIdx.x;
    const int r   = tid >> 2;       // q row within tile 0..63
    const int l4  = tid & 3;
    const int s   = qb * QT + r;

    const float* qrow = qkv + (size_t)s * QKVN + h * 384;
    float q[32];
#pragma unroll
    for (int j = 0; j < 8; ++j) {
        float4 v = *reinterpret_cast<const float4*>(&qrow[j * 16 + l4 * 4]);
        q[4 * j + 0] = v.x; q[4 * j + 1] = v.y;
        q[4 * j + 2] = v.z; q[4 * j + 3] = v.w;
    }

    float m = -1e30f, l = 0.f;
    float o[32];
#pragma unroll
    for (int j = 0; j < 32; ++j) o[j] = 0.f;
    const float scale = 0.08838834764831845f;   // 1/sqrt(128)

    for (int kb = 0; kb <= qb; ++kb) {
        __syncthreads();   // protect previous tile reads before overwrite
#pragma unroll
        for (int i2 = 0; i2 < 8; ++i2) {
            const int i = tid + i2 * 256;       // 0..2047 float4 slots
            const int t = i >> 5, c = i & 31;
            const float* base = qkv + (size_t)(kb * KT + t) * QKVN + h * 384;
            reinterpret_cast<float4*>(Ks)[t * 32 + c] =
                reinterpret_cast<const float4*>(base + 128)[c];
            reinterpret_cast<float4*>(Vs)[t * 32 + c] =
                reinterpret_cast<const float4*>(base + 256)[c];
        }
        __syncthreads();

        const bool diag = (kb == qb);
#pragma unroll 1
        for (int tc = 0; tc < KT; tc += 16) {
            float sc[16];
#pragma unroll
            for (int u = 0; u < 16; ++u) {
                const int t = tc + u;
                const float* kr = Ks + t * HDIM + l4 * 4;
                float s0 = 0.f, s1 = 0.f, s2 = 0.f, s3 = 0.f;
#pragma unroll
                for (int j = 0; j < 8; ++j) {
                    float4 k4 = *reinterpret_cast<const float4*>(kr + j * 16);
                    s0 = fmaf(q[4 * j + 0], k4.x, s0);
                    s1 = fmaf(q[4 * j + 1], k4.y, s1);
                    s2 = fmaf(q[4 * j + 2], k4.z, s2);
                    s3 = fmaf(q[4 * j + 3], k4.w, s3);
                }
                float sum = (s0 + s1) + (s2 + s3);
                sum += __shfl_xor_sync(0xffffffffu, sum, 1);
                sum += __shfl_xor_sync(0xffffffffu, sum, 2);
                sc[u] = (!diag || t <= r) ? sum * scale : -1e30f;
            }
            float mt = sc[0];
#pragma unroll
            for (int u = 1; u < 16; ++u) mt = fmaxf(mt, sc[u]);
            const float mnew = fmaxf(m, mt);
            const float corr = __expf(m - mnew);
            l *= corr;
#pragma unroll
            for (int u = 0; u < 16; ++u) { sc[u] = __expf(sc[u] - mnew); l += sc[u]; }
#pragma unroll
            for (int j = 0; j < 32; ++j) o[j] *= corr;
#pragma unroll
            for (int u = 0; u < 16; ++u) {
                const float* vr = Vs + (tc + u) * HDIM + l4 * 4;
                const float p = sc[u];
#pragma unroll
                for (int j = 0; j < 8; ++j) {
                    float4 v4 = *reinterpret_cast<const float4*>(vr + j * 16);
                    o[4 * j + 0] = fmaf(p, v4.x, o[4 * j + 0]);
                    o[4 * j + 1] = fmaf(p, v4.y, o[4 * j + 1]);
                    o[4 * j + 2] = fmaf(p, v4.z, o[4 * j + 2]);
                    o[4 * j + 3] = fmaf(p, v4.w, o[4 * j + 3]);
                }
            }
            m = mnew;
        }
    }

    const float inv = 1.0f / l;
    float* outp = ctx + (size_t)s * Hdim + h * HDIM;
#pragma unroll
    for (int j = 0; j < 8; ++j) {
        float4 v;
        v.x = o[4 * j + 0] * inv; v.y = o[4 * j + 1] * inv;
        v.z = o[4 * j + 2] * inv; v.w = o[4 * j + 3] * inv;
        *reinterpret_cast<float4*>(&outp[j * 16 + l4 * 4]) = v;
    }
}

// ---------------------------------------------------------------------------
// Launch: QKV gemm -> RoPE -> flash attention -> dense gemm
// Inputs (metadata order): hidden_states, attention_mask, W_qkv, b_qkv,
//                          W_dense, b_dense.  attention_mask (causal) implied.
// ---------------------------------------------------------------------------
extern "C" void kernel_launch(void* const* d_in, const int* in_sizes, int n_in,
                              void* d_out, int out_size) {
    const float* hidden  = (const float*)d_in[0];
    const float* W_qkv   = (const float*)d_in[2];
    const float* b_qkv   = (const float*)d_in[3];
    const float* W_dense = (const float*)d_in[4];
    const float* b_dense = (const float*)d_in[5];
    float* out = (float*)d_out;

    float *qkv = nullptr, *ctx = nullptr;
    cudaGetSymbolAddress((void**)&qkv, g_qkv);
    cudaGetSymbolAddress((void**)&ctx, g_ctx);

    cudaFuncSetAttribute(reinterpret_cast<const void*>(flash_attn),
                         cudaFuncAttributeMaxDynamicSharedMemorySize, 65536);

    dim3 g1(QKVN / BN, Sdim / BM);
    gemm_tf32<<<g1, 256>>>(hidden, W_qkv, b_qkv, qkv, Sdim, QKVN, Hdim);

    rope_kernel<<<(Sdim * NHEAD * 16 + 255) / 256, 256>>>(qkv);

    dim3 g2(Sdim / QT, NHEAD);
    flash_attn<<<g2, 256, 65536>>>(qkv, ctx);

    dim3 g3(Hdim / BN, Sdim / BM);
    gemm_tf32<<<g3, 256>>>(ctx, W_dense, b_dense, out, Sdim, Hdim, Hdim);
}

// round 7
// speedup vs baseline: 1.7790x; 1.7790x over previous
#include <cuda_runtime.h>
#include <math.h>
#include <stdint.h>

// Problem constants
#define Sdim  2048
#define Hdim  4096
#define NHEAD 32
#define HDIM  128
#define QKVN  12288   // 3*Hdim

// Scratch (allocation-free rule: __device__ globals)
__device__ float  g_qkv[(size_t)Sdim * QKVN];    // ~100.7 MB
__device__ float  g_ctx[(size_t)Sdim * Hdim];    // ~33.6 MB
__device__ float2 g_rope[Sdim * 16];             // cos/sin table

__device__ __forceinline__ unsigned f2tf32(float x) {
    unsigned u;
    asm("cvt.rna.tf32.f32 %0, %1;" : "=r"(u) : "f"(x));
    return u;
}
__device__ __forceinline__ unsigned tf32bits(unsigned fb) {
    unsigned u;
    asm("cvt.rna.tf32.f32 %0, %1;" : "=r"(u) : "f"(__uint_as_float(fb)));
    return u;
}
__device__ __forceinline__ void mma1688(float* c, unsigned a0, unsigned a1,
                                        unsigned a2, unsigned a3,
                                        unsigned b0, unsigned b1) {
    asm volatile(
        "mma.sync.aligned.m16n8k8.row.col.f32.tf32.tf32.f32 "
        "{%0,%1,%2,%3}, {%4,%5,%6,%7}, {%8,%9}, {%0,%1,%2,%3};\n"
        : "+f"(c[0]), "+f"(c[1]), "+f"(c[2]), "+f"(c[3])
        : "r"(a0), "r"(a1), "r"(a2), "r"(a3), "r"(b0), "r"(b1));
}
__device__ __forceinline__ void cp16(unsigned saddr, const void* gptr) {
    asm volatile("cp.async.cg.shared.global [%0], [%1], 16;" ::
                 "r"(saddr), "l"(gptr));
}

// ---------------------------------------------------------------------------
// TF32 tensor-core GEMM:  C[M,N] = A[M,K] @ B[N,K]^T + bias[N]
// CTA tile 128x128x32, 8 warps (2x4), warp 64x32. (measured 581us for QKV)
// ---------------------------------------------------------------------------
#define BM 128
#define BN 128
#define BK 32
#define KSTR 36

__global__ __launch_bounds__(256, 1) void gemm_tf32(
    const float* __restrict__ A, const float* __restrict__ B,
    const float* __restrict__ bias, float* __restrict__ C,
    int M, int N, int K)
{
    __shared__ unsigned As[BM * KSTR];
    __shared__ unsigned Bs[BN * KSTR];

    const int tid  = threadIdx.x;
    const int warp = tid >> 5;
    const int lane = tid & 31;
    const int wm = warp >> 2;
    const int wn = warp & 3;
    const int g  = lane >> 2;
    const int tg = lane & 3;
    const int bm = blockIdx.y * BM;
    const int bn = blockIdx.x * BN;
    const int lr = tid >> 3;
    const int lc = tid & 7;

    float acc[4][4][4];
#pragma unroll
    for (int i = 0; i < 4; ++i)
#pragma unroll
        for (int j = 0; j < 4; ++j)
#pragma unroll
            for (int c = 0; c < 4; ++c) acc[i][j][c] = 0.f;

    float4 ra[4], rb[4];

#define LOAD_TILES(k0)                                                          \
    {                                                                           \
        _Pragma("unroll")                                                       \
        for (int i = 0; i < 4; ++i) {                                           \
            ra[i] = *reinterpret_cast<const float4*>(                           \
                &A[(size_t)(bm + lr + 32 * i) * K + (k0) + lc * 4]);            \
            rb[i] = *reinterpret_cast<const float4*>(                           \
                &B[(size_t)(bn + lr + 32 * i) * K + (k0) + lc * 4]);            \
        }                                                                       \
    }
#define STORE_TILES()                                                           \
    {                                                                           \
        _Pragma("unroll")                                                       \
        for (int i = 0; i < 4; ++i) {                                           \
            unsigned* pa = &As[(lr + 32 * i) * KSTR + lc * 4];                  \
            pa[0] = f2tf32(ra[i].x); pa[1] = f2tf32(ra[i].y);                   \
            pa[2] = f2tf32(ra[i].z); pa[3] = f2tf32(ra[i].w);                   \
            unsigned* pb = &Bs[(lr + 32 * i) * KSTR + lc * 4];                  \
            pb[0] = f2tf32(rb[i].x); pb[1] = f2tf32(rb[i].y);                   \
            pb[2] = f2tf32(rb[i].z); pb[3] = f2tf32(rb[i].w);                   \
        }                                                                       \
    }

    LOAD_TILES(0);
    STORE_TILES();
    __syncthreads();

    const int nIter = K / BK;
    for (int it = 0; it < nIter; ++it) {
        const bool hasNext = (it + 1 < nIter);
        if (hasNext) LOAD_TILES((it + 1) * BK);

#pragma unroll
        for (int ks = 0; ks < 4; ++ks) {
            unsigned af[4][4], bf[4][2];
#pragma unroll
            for (int i = 0; i < 4; ++i) {
                const int r = wm * 64 + i * 16 + g;
                af[i][0] = As[r * KSTR + ks * 8 + tg];
                af[i][1] = As[(r + 8) * KSTR + ks * 8 + tg];
                af[i][2] = As[r * KSTR + ks * 8 + tg + 4];
                af[i][3] = As[(r + 8) * KSTR + ks * 8 + tg + 4];
            }
#pragma unroll
            for (int j = 0; j < 4; ++j) {
                const int rn = wn * 32 + j * 8 + g;
                bf[j][0] = Bs[rn * KSTR + ks * 8 + tg];
                bf[j][1] = Bs[rn * KSTR + ks * 8 + tg + 4];
            }
#pragma unroll
            for (int i = 0; i < 4; ++i)
#pragma unroll
                for (int j = 0; j < 4; ++j)
                    mma1688(acc[i][j], af[i][0], af[i][1], af[i][2], af[i][3],
                            bf[j][0], bf[j][1]);
        }
        __syncthreads();
        if (hasNext) {
            STORE_TILES();
            __syncthreads();
        }
    }

#pragma unroll
    for (int i = 0; i < 4; ++i) {
        const int row = bm + wm * 64 + i * 16 + g;
#pragma unroll
        for (int j = 0; j < 4; ++j) {
            const int col = bn + wn * 32 + j * 8 + tg * 2;
            const float b0 = bias[col], b1 = bias[col + 1];
            C[(size_t)row * N + col]           = acc[i][j][0] + b0;
            C[(size_t)row * N + col + 1]       = acc[i][j][1] + b1;
            C[(size_t)(row + 8) * N + col]     = acc[i][j][2] + b0;
            C[(size_t)(row + 8) * N + col + 1] = acc[i][j][3] + b1;
        }
    }
#undef LOAD_TILES
#undef STORE_TILES
}

// ---------------------------------------------------------------------------
// RoPE: precompute cos/sin table (double precision, once), then fp32 apply.
// ---------------------------------------------------------------------------
__global__ void rope_table_kernel(float2* __restrict__ tab) {
    const int idx = blockIdx.x * blockDim.x + threadIdx.x;
    if (idx >= Sdim * 16) return;
    const int i = idx & 15;
    const int s = idx >> 4;
    const double invf = pow(10000.0, -((double)i / 16.0));
    double sd, cd;
    sincos((double)s * invf, &sd, &cd);
    tab[idx] = make_float2((float)cd, (float)sd);
}

__global__ void rope_apply_kernel(float* __restrict__ qkv,
                                  const float2* __restrict__ tab) {
    const int idx = blockIdx.x * blockDim.x + threadIdx.x;
    if (idx >= Sdim * NHEAD * 16) return;
    const int i = idx & 15;
    const int h = (idx >> 4) & 31;
    const int s = idx >> 9;
    const float2 cs = tab[s * 16 + i];
    const float c = cs.x, sn = cs.y;

    float* base = qkv + (size_t)s * QKVN + h * 384;
    {   // q
        const float x0 = base[i], x1 = base[i + 16];
        base[i]      = x0 * c - x1 * sn;
        base[i + 16] = x1 * c + x0 * sn;
    }
    {   // k
        const float x0 = base[128 + i], x1 = base[128 + i + 16];
        base[128 + i]      = x0 * c - x1 * sn;
        base[128 + i + 16] = x1 * c + x0 * sn;
    }
}

// ---------------------------------------------------------------------------
// MMA-based causal flash attention (tf32).
// CTA = (head, 128 q-rows). 8 warps x 16 rows. KT=64, cp.async double buffer.
// Scores: single tf32 MMA. PV: P split hi/lo (2 MMAs) vs tf32 V.
// ---------------------------------------------------------------------------
#define FQT   128
#define FKT   64
#define QSTRW 132   // Q smem stride (words)
#define KSTRW 132   // K smem stride
#define VSTRW 136   // V smem stride
#define FSMEM ((FQT*QSTRW + 2*FKT*KSTRW + 2*FKT*VSTRW) * 4)  // 204800 B

__global__ __launch_bounds__(256, 1) void flash_attn_mma(
    const float* __restrict__ qkv, float* __restrict__ ctx)
{
    extern __shared__ unsigned sh[];
    unsigned* Qs = sh;
    unsigned* Ks = sh + FQT * QSTRW;              // 2 buffers, fp32 -> tf32
    unsigned* Vs = Ks + 2 * FKT * KSTRW;          // 2 buffers

    const unsigned shbase  = (unsigned)__cvta_generic_to_shared(sh);
    const unsigned ks_base = shbase + FQT * QSTRW * 4;
    const unsigned vs_base = ks_base + 2 * FKT * KSTRW * 4;

    const int h    = blockIdx.y;
    const int qb   = (gridDim.x - 1) - blockIdx.x;   // heavy CTAs first
    const int tid  = threadIdx.x;
    const int warp = tid >> 5;
    const int lane = tid & 31;
    const int g    = lane >> 2;
    const int tg   = lane & 3;
    const int srcA = (lane & 28) + (tg >> 1);
    const int srcB = srcA + 2;
    const int psel = tg & 1;

    const float* qbase = qkv + (size_t)(qb * FQT) * QKVN + h * 384;

    // ---- Q -> tf32 smem (once per CTA) ----
#pragma unroll
    for (int i = 0; i < 16; ++i) {
        const int idx = tid + 256 * i;       // 0..4095 float4 slots
        const int row = idx >> 5, c4 = idx & 31;
        float4 v = *reinterpret_cast<const float4*>(
            qbase + (size_t)row * QKVN + c4 * 4);
        unsigned* p = Qs + row * QSTRW + c4 * 4;
        p[0] = f2tf32(v.x); p[1] = f2tf32(v.y);
        p[2] = f2tf32(v.z); p[3] = f2tf32(v.w);
    }

    const int nkt = 2 * (qb + 1);

    // ---- tile loader (cp.async, raw fp32) ----
#define LOAD_TILE(buf, kb)                                                      \
    {                                                                           \
        const float* kb_g = qkv + (size_t)((kb) * FKT) * QKVN + h * 384 + 128;  \
        const unsigned ksd = ks_base + (buf) * (FKT * KSTRW * 4);               \
        const unsigned vsd = vs_base + (buf) * (FKT * VSTRW * 4);               \
        _Pragma("unroll")                                                       \
        for (int i = 0; i < 8; ++i) {                                           \
            const int idx = tid + 256 * i;                                      \
            const int row = idx >> 5, c = idx & 31;                             \
            cp16(ksd + row * (KSTRW * 4) + c * 16,                              \
                 kb_g + (size_t)row * QKVN + c * 4);                            \
            cp16(vsd + row * (VSTRW * 4) + c * 16,                              \
                 kb_g + 128 + (size_t)row * QKVN + c * 4);                      \
        }                                                                       \
        asm volatile("cp.async.commit_group;");                                 \
    }

    // ---- in-place fp32 -> tf32 conversion of a K/V buffer ----
#define CVT_TILE(buf)                                                           \
    {                                                                           \
        uint4* kp = reinterpret_cast<uint4*>(Ks + (buf) * FKT * KSTRW);         \
        uint4* vp = reinterpret_cast<uint4*>(Vs + (buf) * FKT * VSTRW);         \
        _Pragma("unroll")                                                       \
        for (int i = 0; i < 9; ++i) {                                           \
            const int idx = tid + 256 * i;                                      \
            if (idx < (FKT * KSTRW) / 4) {                                      \
                uint4 v = kp[idx];                                              \
                v.x = tf32bits(v.x); v.y = tf32bits(v.y);                       \
                v.z = tf32bits(v.z); v.w = tf32bits(v.w);                       \
                kp[idx] = v;                                                    \
            }                                                                   \
            if (idx < (FKT * VSTRW) / 4) {                                      \
                uint4 v = vp[idx];                                              \
                v.x = tf32bits(v.x); v.y = tf32bits(v.y);                       \
                v.z = tf32bits(v.z); v.w = tf32bits(v.w);                       \
                vp[idx] = v;                                                    \
            }                                                                   \
        }                                                                       \
    }

    LOAD_TILE(0, 0);
    asm volatile("cp.async.wait_group 0;");
    __syncthreads();
    CVT_TILE(0);
    __syncthreads();

    float oacc[16][4];
#pragma unroll
    for (int n = 0; n < 16; ++n)
#pragma unroll
        for (int c = 0; c < 4; ++c) oacc[n][c] = 0.f;

    float m0 = -1e30f, m1 = -1e30f, l0 = 0.f, l1 = 0.f;
    const float scale = 0.08838834764831845f;   // 1/sqrt(128)
    const int row0 = qb * FQT + warp * 16 + g;
    const int row1 = row0 + 8;

    for (int kb = 0; kb < nkt; ++kb) {
        const int b = kb & 1;
        if (kb + 1 < nkt) LOAD_TILE(b ^ 1, kb + 1);

        const unsigned* Kb = Ks + b * FKT * KSTRW;
        const unsigned* Vb = Vs + b * FKT * VSTRW;

        const bool fully_masked = (kb * FKT > qb * FQT + warp * 16 + 15);
        if (!fully_masked) {
            // ---- scores S = Q K^T (single tf32) ----
            float sacc[8][4];
#pragma unroll
            for (int n = 0; n < 8; ++n)
#pragma unroll
                for (int c = 0; c < 4; ++c) sacc[n][c] = 0.f;

            const unsigned* qa = Qs + (warp * 16 + g) * QSTRW + tg;
#pragma unroll
            for (int ks = 0; ks < 16; ++ks) {
                const unsigned a0 = qa[ks * 8];
                const unsigned a1 = qa[ks * 8 + 8 * QSTRW];
                const unsigned a2 = qa[ks * 8 + 4];
                const unsigned a3 = qa[ks * 8 + 4 + 8 * QSTRW];
                const unsigned* kp = Kb + g * KSTRW + ks * 8 + tg;
#pragma unroll
                for (int n = 0; n < 8; ++n) {
                    const unsigned b0 = kp[(n * 8) * KSTRW];
                    const unsigned b1 = kp[(n * 8) * KSTRW + 4];
                    mma1688(sacc[n], a0, a1, a2, a3, b0, b1);
                }
            }

            // ---- scale + causal mask + online softmax ----
            const bool needmask = (kb * FKT + 63 > qb * FQT + warp * 16);
            float mt0 = -1e30f, mt1 = -1e30f;
#pragma unroll
            for (int n = 0; n < 8; ++n) {
                float s0 = sacc[n][0] * scale, s1 = sacc[n][1] * scale;
                float s2 = sacc[n][2] * scale, s3 = sacc[n][3] * scale;
                if (needmask) {
                    const int c0 = kb * FKT + n * 8 + 2 * tg;
                    if (c0     > row0) s0 = -1e30f;
                    if (c0 + 1 > row0) s1 = -1e30f;
                    if (c0     > row1) s2 = -1e30f;
                    if (c0 + 1 > row1) s3 = -1e30f;
                }
                sacc[n][0] = s0; sacc[n][1] = s1;
                sacc[n][2] = s2; sacc[n][3] = s3;
                mt0 = fmaxf(mt0, fmaxf(s0, s1));
                mt1 = fmaxf(mt1, fmaxf(s2, s3));
            }
            mt0 = fmaxf(mt0, __shfl_xor_sync(0xffffffffu, mt0, 1));
            mt0 = fmaxf(mt0, __shfl_xor_sync(0xffffffffu, mt0, 2));
            mt1 = fmaxf(mt1, __shfl_xor_sync(0xffffffffu, mt1, 1));
            mt1 = fmaxf(mt1, __shfl_xor_sync(0xffffffffu, mt1, 2));

            const float mn0 = fmaxf(m0, mt0), mn1 = fmaxf(m1, mt1);
            const float cr0 = __expf(m0 - mn0), cr1 = __expf(m1 - mn1);
            float ls0 = 0.f, ls1 = 0.f;
#pragma unroll
            for (int n = 0; n < 8; ++n) {
                sacc[n][0] = __expf(sacc[n][0] - mn0);
                sacc[n][1] = __expf(sacc[n][1] - mn0);
                sacc[n][2] = __expf(sacc[n][2] - mn1);
                sacc[n][3] = __expf(sacc[n][3] - mn1);
                ls0 += sacc[n][0] + sacc[n][1];
                ls1 += sacc[n][2] + sacc[n][3];
            }
            ls0 += __shfl_xor_sync(0xffffffffu, ls0, 1);
            ls0 += __shfl_xor_sync(0xffffffffu, ls0, 2);
            ls1 += __shfl_xor_sync(0xffffffffu, ls1, 1);
            ls1 += __shfl_xor_sync(0xffffffffu, ls1, 2);
            l0 = l0 * cr0 + ls0;
            l1 = l1 * cr1 + ls1;
            m0 = mn0; m1 = mn1;

#pragma unroll
            for (int n = 0; n < 16; ++n) {
                oacc[n][0] *= cr0; oacc[n][1] *= cr0;
                oacc[n][2] *= cr1; oacc[n][3] *= cr1;
            }

            // ---- PV: O += P V  (P split hi/lo, V tf32) ----
#pragma unroll
            for (int ks = 0; ks < 8; ++ks) {
                const float v00 = __shfl_sync(0xffffffffu, sacc[ks][0], srcA);
                const float v01 = __shfl_sync(0xffffffffu, sacc[ks][1], srcA);
                const float v02 = __shfl_sync(0xffffffffu, sacc[ks][2], srcA);
                const float v03 = __shfl_sync(0xffffffffu, sacc[ks][3], srcA);
                const float v10 = __shfl_sync(0xffffffffu, sacc[ks][0], srcB);
                const float v11 = __shfl_sync(0xffffffffu, sacc[ks][1], srcB);
                const float v12 = __shfl_sync(0xffffffffu, sacc[ks][2], srcB);
                const float v13 = __shfl_sync(0xffffffffu, sacc[ks][3], srcB);
                const float pa0 = psel ? v01 : v00;
                const float pa1 = psel ? v03 : v02;
                const float pa2 = psel ? v11 : v10;
                const float pa3 = psel ? v13 : v12;

                unsigned ah[4], al[4];
                ah[0] = f2tf32(pa0); al[0] = f2tf32(pa0 - __uint_as_float(ah[0]));
                ah[1] = f2tf32(pa1); al[1] = f2tf32(pa1 - __uint_as_float(ah[1]));
                ah[2] = f2tf32(pa2); al[2] = f2tf32(pa2 - __uint_as_float(ah[2]));
                ah[3] = f2tf32(pa3); al[3] = f2tf32(pa3 - __uint_as_float(ah[3]));

                const unsigned* vp = Vb + (ks * 8 + tg) * VSTRW + g;
#pragma unroll
                for (int n = 0; n < 16; ++n) {
                    const unsigned b0 = vp[n * 8];
                    const unsigned b1 = vp[n * 8 + 4 * VSTRW];
                    mma1688(oacc[n], ah[0], ah[1], ah[2], ah[3], b0, b1);
                    mma1688(oacc[n], al[0], al[1], al[2], al[3], b0, b1);
                }
            }
        }

        asm volatile("cp.async.wait_group 0;");
        __syncthreads();
        if (kb + 1 < nkt) {
            CVT_TILE(b ^ 1);
            __syncthreads();
        }
    }

    // ---- normalize + store ----
    const float inv0 = 1.0f / l0, inv1 = 1.0f / l1;
    float* op0 = ctx + (size_t)row0 * Hdim + h * HDIM;
    float* op1 = op0 + (size_t)8 * Hdim;
#pragma unroll
    for (int n = 0; n < 16; ++n) {
        const int col = n * 8 + 2 * tg;
        float2 w0 = make_float2(oacc[n][0] * inv0, oacc[n][1] * inv0);
        float2 w1 = make_float2(oacc[n][2] * inv1, oacc[n][3] * inv1);
        *reinterpret_cast<float2*>(op0 + col) = w0;
        *reinterpret_cast<float2*>(op1 + col) = w1;
    }
#undef LOAD_TILE
#undef CVT_TILE
}

// ---------------------------------------------------------------------------
// Launch: QKV gemm -> RoPE table/apply -> MMA flash attention -> dense gemm
// ---------------------------------------------------------------------------
extern "C" void kernel_launch(void* const* d_in, const int* in_sizes, int n_in,
                              void* d_out, int out_size) {
    const float* hidden  = (const float*)d_in[0];
    const float* W_qkv   = (const float*)d_in[2];
    const float* b_qkv   = (const float*)d_in[3];
    const float* W_dense = (const float*)d_in[4];
    const float* b_dense = (const float*)d_in[5];
    float* out = (float*)d_out;

    float*  qkv = nullptr;
    float*  ctx = nullptr;
    float2* tab = nullptr;
    cudaGetSymbolAddress((void**)&qkv, g_qkv);
    cudaGetSymbolAddress((void**)&ctx, g_ctx);
    cudaGetSymbolAddress((void**)&tab, g_rope);

    cudaFuncSetAttribute(reinterpret_cast<const void*>(flash_attn_mma),
                         cudaFuncAttributeMaxDynamicSharedMemorySize, FSMEM);

    dim3 g1(QKVN / BN, Sdim / BM);
    gemm_tf32<<<g1, 256>>>(hidden, W_qkv, b_qkv, qkv, Sdim, QKVN, Hdim);

    rope_table_kernel<<<(Sdim * 16 + 255) / 256, 256>>>(tab);
    rope_apply_kernel<<<(Sdim * NHEAD * 16 + 255) / 256, 256>>>(qkv, tab);

    dim3 g2(Sdim / FQT, NHEAD);
    flash_attn_mma<<<g2, 256, FSMEM>>>(qkv, ctx);

    dim3 g3(Hdim / BN, Sdim / BM);
    gemm_tf32<<<g3, 256>>>(ctx, W_dense, b_dense, out, Sdim, Hdim, Hdim);
}

// round 12
// speedup vs baseline: 1.8732x; 1.0530x over previous
#include <cuda_runtime.h>
#include <math.h>
#include <stdint.h>

// Problem constants
#define Sdim  2048
#define Hdim  4096
#define NHEAD 32
#define HDIM  128
#define QKVN  12288   // 3*Hdim

// Scratch (allocation-free rule: __device__ globals) — 134 MB total,
// identical footprint to the round-7 kernel that is proven to run.
__device__ float  g_qkv[(size_t)Sdim * QKVN];    // ~100.7 MB
__device__ float  g_ctx[(size_t)Sdim * Hdim];    // ~33.6 MB
__device__ float2 g_rope[Sdim * 16];             // cos/sin table

__device__ __forceinline__ unsigned f2tf32(float x) {
    unsigned u;
    asm("cvt.rna.tf32.f32 %0, %1;" : "=r"(u) : "f"(x));
    return u;
}
__device__ __forceinline__ unsigned tf32bits(unsigned fb) {
    unsigned u;
    asm("cvt.rna.tf32.f32 %0, %1;" : "=r"(u) : "f"(__uint_as_float(fb)));
    return u;
}
__device__ __forceinline__ void mma1688(float* c, unsigned a0, unsigned a1,
                                        unsigned a2, unsigned a3,
                                        unsigned b0, unsigned b1) {
    asm volatile(
        "mma.sync.aligned.m16n8k8.row.col.f32.tf32.tf32.f32 "
        "{%0,%1,%2,%3}, {%4,%5,%6,%7}, {%8,%9}, {%0,%1,%2,%3};\n"
        : "+f"(c[0]), "+f"(c[1]), "+f"(c[2]), "+f"(c[3])
        : "r"(a0), "r"(a1), "r"(a2), "r"(a3), "r"(b0), "r"(b1));
}
__device__ __forceinline__ void cp16(unsigned saddr, const void* gptr) {
    asm volatile("cp.async.cg.shared.global [%0], [%1], 16;" ::
                 "r"(saddr), "l"(gptr));
}
__device__ __forceinline__ uint32_t smem_u32(const void* p) {
    uint32_t a;
    asm("{ .reg .u64 t; cvta.to.shared.u64 t, %1; cvt.u32.u64 %0, t; }"
        : "=r"(a) : "l"(p));
    return a;
}

// ---------------------------------------------------------------------------
// TF32 tensor-core GEMM v3:  C[M,N] = A[M,K] @ B[N,K]^T + bias[N]
// fp32 inputs. cp.async 3-stage ring -> in-smem fp32->tf32 sweep ->
// ldmatrix.x4 fragment loads -> mma. 2 CTAs/SM. CTA tile 128x128, BK=32.
// 8 warps (2x4), warp tile 64x32. smem row stride 144B.
// ---------------------------------------------------------------------------
#define GST_B 144                  // smem row stride bytes
#define GBUF  (128 * GST_B)        // one matrix tile buffer: 18432 B
#define G3SMEM (6 * GBUF)          // 3 stages x (A + B) = 110592 B

__global__ __launch_bounds__(256, 2) void gemm_tc3(
    const float* __restrict__ A, const float* __restrict__ B,
    const float* __restrict__ bias, float* __restrict__ C,
    int M, int N, int K)
{
    extern __shared__ unsigned char gsm[];
    const uint32_t sb = smem_u32(gsm);

    const int tid  = threadIdx.x;
    const int warp = tid >> 5;
    const int lane = tid & 31;
    const int wm = warp >> 2;       // 0..1
    const int wn = warp & 3;        // 0..3
    const int g  = lane >> 2;
    const int tg = lane & 3;
    const int bm = blockIdx.y * 128;
    const int bn = blockIdx.x * 128;

    // cp.async: thread -> 4 rows (lrow + 32*i), one 16B chunk (lc) each
    const int lrow = tid >> 3;      // 0..31
    const int lc   = tid & 7;       // 0..7
    const float* agp = A + (size_t)(bm + lrow) * K + lc * 4;
    const float* bgp = B + (size_t)(bn + lrow) * K + lc * 4;
    const uint32_t sOff = (uint32_t)lrow * GST_B + lc * 16;

    const int nIter = K >> 5;       // K/32

#define ISSUE(itx)                                                             \
    {                                                                          \
        const uint32_t _ab = sb + ((itx) % 3) * (2 * GBUF);                    \
        const uint32_t _bb = _ab + GBUF;                                       \
        const int _k0 = (itx) * 32;                                            \
        _Pragma("unroll")                                                      \
        for (int i = 0; i < 4; ++i) {                                          \
            cp16(_ab + sOff + i * (32 * GST_B),                                \
                 agp + (size_t)(32 * i) * K + _k0);                            \
            cp16(_bb + sOff + i * (32 * GST_B),                                \
                 bgp + (size_t)(32 * i) * K + _k0);                            \
        }                                                                      \
        asm volatile("cp.async.commit_group;");                                \
    }

    ISSUE(0);
    ISSUE(1);

    float acc[4][4][4];
#pragma unroll
    for (int i = 0; i < 4; ++i)
#pragma unroll
        for (int j = 0; j < 4; ++j)
#pragma unroll
            for (int c = 0; c < 4; ++c) acc[i][j][c] = 0.f;

    // ldmatrix per-thread byte offsets relative to buffer base.
    // A x4 tiles: (rows g, k0-3), (rows g+8, k0-3), (g, k4-7), (g+8, k4-7)
    const uint32_t aOff =
        (uint32_t)(wm * 64 + ((lane >> 3) & 1) * 8 + (lane & 7)) * GST_B +
        (lane >> 4) * 16;
    // B x4 tiles: (n rows 0-7, k0-3), (rows 0-7, k4-7), (rows 8-15, k0-3), (8-15, k4-7)
    const uint32_t bOff =
        (uint32_t)(wn * 32 + ((lane >> 4) & 1) * 8 + (lane & 7)) * GST_B +
        ((lane >> 3) & 1) * 16;

    for (int it = 0; it < nIter; ++it) {
        if (it + 1 == nIter)
            asm volatile("cp.async.wait_group 0;" ::: "memory");
        else
            asm volatile("cp.async.wait_group 1;" ::: "memory");
        __syncthreads();                     // buf(it) visible; prev reads done
        if (it + 2 < nIter) ISSUE(it + 2);   // overwrites buf(it-1): safe

        const uint32_t ab = sb + (it % 3) * (2 * GBUF);
        const uint32_t bb = ab + GBUF;

        // in-place fp32 -> tf32 sweep over buf(it): 2304 uint4 / 256 thr = 9
        {
            uint4* tp = reinterpret_cast<uint4*>(gsm + (it % 3) * (2 * GBUF));
#pragma unroll
            for (int i = 0; i < 9; ++i) {
                uint4 v = tp[tid + 256 * i];
                v.x = tf32bits(v.x); v.y = tf32bits(v.y);
                v.z = tf32bits(v.z); v.w = tf32bits(v.w);
                tp[tid + 256 * i] = v;
            }
        }
        __syncthreads();                     // cvt done before ldmatrix

#pragma unroll
        for (int ks = 0; ks < 4; ++ks) {
            unsigned af[4][4], bf[4][2];
#pragma unroll
            for (int i = 0; i < 4; ++i) {
                asm volatile(
                    "ldmatrix.sync.aligned.m8n8.x4.shared.b16 "
                    "{%0,%1,%2,%3}, [%4];"
                    : "=r"(af[i][0]), "=r"(af[i][1]),
                      "=r"(af[i][2]), "=r"(af[i][3])
                    : "r"(ab + aOff + i * (16 * GST_B) + ks * 32));
            }
#pragma unroll
            for (int jp = 0; jp < 2; ++jp) {
                asm volatile(
                    "ldmatrix.sync.aligned.m8n8.x4.shared.b16 "
                    "{%0,%1,%2,%3}, [%4];"
                    : "=r"(bf[2 * jp][0]), "=r"(bf[2 * jp][1]),
                      "=r"(bf[2 * jp + 1][0]), "=r"(bf[2 * jp + 1][1])
                    : "r"(bb + bOff + jp * (16 * GST_B) + ks * 32));
            }
#pragma unroll
            for (int i = 0; i < 4; ++i)
#pragma unroll
                for (int j = 0; j < 4; ++j)
                    mma1688(acc[i][j], af[i][0], af[i][1], af[i][2], af[i][3],
                            bf[j][0], bf[j][1]);
        }
    }
#undef ISSUE

    // Epilogue: c0:(g,2tg) c1:(g,2tg+1) c2:(g+8,2tg) c3:(g+8,2tg+1)
#pragma unroll
    for (int i = 0; i < 4; ++i) {
        const int row = bm + wm * 64 + i * 16 + g;
#pragma unroll
        for (int j = 0; j < 4; ++j) {
            const int col = bn + wn * 32 + j * 8 + tg * 2;
            const float b0 = bias[col], b1 = bias[col + 1];
            C[(size_t)row * N + col]           = acc[i][j][0] + b0;
            C[(size_t)row * N + col + 1]       = acc[i][j][1] + b1;
            C[(size_t)(row + 8) * N + col]     = acc[i][j][2] + b0;
            C[(size_t)(row + 8) * N + col + 1] = acc[i][j][3] + b1;
        }
    }
}

// ---------------------------------------------------------------------------
// RoPE: precompute cos/sin table (double precision, once), then fp32 apply.
// ---------------------------------------------------------------------------
__global__ void rope_table_kernel(float2* __restrict__ tab) {
    const int idx = blockIdx.x * blockDim.x + threadIdx.x;
    if (idx >= Sdim * 16) return;
    const int i = idx & 15;
    const int s = idx >> 4;
    const double invf = pow(10000.0, -((double)i / 16.0));
    double sd, cd;
    sincos((double)s * invf, &sd, &cd);
    tab[idx] = make_float2((float)cd, (float)sd);
}

__global__ void rope_apply_kernel(float* __restrict__ qkv,
                                  const float2* __restrict__ tab) {
    const int idx = blockIdx.x * blockDim.x + threadIdx.x;
    if (idx >= Sdim * NHEAD * 16) return;
    const int i = idx & 15;
    const int h = (idx >> 4) & 31;
    const int s = idx >> 9;
    const float2 cs = tab[s * 16 + i];
    const float c = cs.x, sn = cs.y;

    float* base = qkv + (size_t)s * QKVN + h * 384;
    {   // q
        const float x0 = base[i], x1 = base[i + 16];
        base[i]      = x0 * c - x1 * sn;
        base[i + 16] = x1 * c + x0 * sn;
    }
    {   // k
        const float x0 = base[128 + i], x1 = base[128 + i + 16];
        base[128 + i]      = x0 * c - x1 * sn;
        base[128 + i + 16] = x1 * c + x0 * sn;
    }
}

// ---------------------------------------------------------------------------
// MMA-based causal flash attention (tf32).  (unchanged, measured 443.7us)
// ---------------------------------------------------------------------------
#define FQT   128
#define FKT   64
#define QSTRW 132
#define KSTRW 132
#define VSTRW 136
#define FSMEM ((FQT*QSTRW + 2*FKT*KSTRW + 2*FKT*VSTRW) * 4)  // 204800 B

__global__ __launch_bounds__(256, 1) void flash_attn_mma(
    const float* __restrict__ qkv, float* __restrict__ ctx)
{
    extern __shared__ unsigned sh[];
    unsigned* Qs = sh;
    unsigned* Ks = sh + FQT * QSTRW;
    unsigned* Vs = Ks + 2 * FKT * KSTRW;

    const unsigned shbase  = smem_u32(sh);
    const unsigned ks_base = shbase + FQT * QSTRW * 4;
    const unsigned vs_base = ks_base + 2 * FKT * KSTRW * 4;

    const int h    = blockIdx.y;
    const int qb   = (gridDim.x - 1) - blockIdx.x;
    const int tid  = threadIdx.x;
    const int warp = tid >> 5;
    const int lane = tid & 31;
    const int g    = lane >> 2;
    const int tg   = lane & 3;
    const int srcA = (lane & 28) + (tg >> 1);
    const int srcB = srcA + 2;
    const int psel = tg & 1;

    const float* qbase = qkv + (size_t)(qb * FQT) * QKVN + h * 384;

#pragma unroll
    for (int i = 0; i < 16; ++i) {
        const int idx = tid + 256 * i;
        const int row = idx >> 5, c4 = idx & 31;
        float4 v = *reinterpret_cast<const float4*>(
            qbase + (size_t)row * QKVN + c4 * 4);
        unsigned* p = Qs + row * QSTRW + c4 * 4;
        p[0] = f2tf32(v.x); p[1] = f2tf32(v.y);
        p[2] = f2tf32(v.z); p[3] = f2tf32(v.w);
    }

    const int nkt = 2 * (qb + 1);

#define LOAD_TILE(buf, kb)                                                      \
    {                                                                           \
        const float* kb_g = qkv + (size_t)((kb) * FKT) * QKVN + h * 384 + 128;  \
        const unsigned ksd = ks_base + (buf) * (FKT * KSTRW * 4);               \
        const unsigned vsd = vs_base + (buf) * (FKT * VSTRW * 4);               \
        _Pragma("unroll")                                                       \
        for (int i = 0; i < 8; ++i) {                                           \
            const int idx = tid + 256 * i;                                      \
            const int row = idx >> 5, c = idx & 31;                             \
            cp16(ksd + row * (KSTRW * 4) + c * 16,                              \
                 kb_g + (size_t)row * QKVN + c * 4);                            \
            cp16(vsd + row * (VSTRW * 4) + c * 16,                              \
                 kb_g + 128 + (size_t)row * QKVN + c * 4);                      \
        }                                                                       \
        asm volatile("cp.async.commit_group;");                                 \
    }
#define CVT_TILE(buf)                                                           \
    {                                                                           \
        uint4* kp = reinterpret_cast<uint4*>(Ks + (buf) * FKT * KSTRW);         \
        uint4* vp = reinterpret_cast<uint4*>(Vs + (buf) * FKT * VSTRW);         \
        _Pragma("unroll")                                                       \
        for (int i = 0; i < 9; ++i) {                                           \
            const int idx = tid + 256 * i;                                      \
            if (idx < (FKT * KSTRW) / 4) {                                      \
                uint4 v = kp[idx];                                              \
                v.x = tf32bits(v.x); v.y = tf32bits(v.y);                       \
                v.z = tf32bits(v.z); v.w = tf32bits(v.w);                       \
                kp[idx] = v;                                                    \
            }                                                                   \
            if (idx < (FKT * VSTRW) / 4) {                                      \
                uint4 v = vp[idx];                                              \
                v.x = tf32bits(v.x); v.y = tf32bits(v.y);                       \
                v.z = tf32bits(v.z); v.w = tf32bits(v.w);                       \
                vp[idx] = v;                                                    \
            }                                                                   \
        }                                                                       \
    }

    LOAD_TILE(0, 0);
    asm volatile("cp.async.wait_group 0;");
    __syncthreads();
    CVT_TILE(0);
    __syncthreads();

    float oacc[16][4];
#pragma unroll
    for (int n = 0; n < 16; ++n)
#pragma unroll
        for (int c = 0; c < 4; ++c) oacc[n][c] = 0.f;

    float m0 = -1e30f, m1 = -1e30f, l0 = 0.f, l1 = 0.f;
    const float scale = 0.08838834764831845f;
    const int row0 = qb * FQT + warp * 16 + g;
    const int row1 = row0 + 8;

    for (int kb = 0; kb < nkt; ++kb) {
        const int b = kb & 1;
        if (kb + 1 < nkt) LOAD_TILE(b ^ 1, kb + 1);

        const unsigned* Kb = Ks + b * FKT * KSTRW;
        const unsigned* Vb = Vs + b * FKT * VSTRW;

        const bool fully_masked = (kb * FKT > qb * FQT + warp * 16 + 15);
        if (!fully_masked) {
            float sacc[8][4];
#pragma unroll
            for (int n = 0; n < 8; ++n)
#pragma unroll
                for (int c = 0; c < 4; ++c) sacc[n][c] = 0.f;

            const unsigned* qa = Qs + (warp * 16 + g) * QSTRW + tg;
#pragma unroll
            for (int ks = 0; ks < 16; ++ks) {
                const unsigned a0 = qa[ks * 8];
                const unsigned a1 = qa[ks * 8 + 8 * QSTRW];
                const unsigned a2 = qa[ks * 8 + 4];
                const unsigned a3 = qa[ks * 8 + 4 + 8 * QSTRW];
                const unsigned* kp = Kb + g * KSTRW + ks * 8 + tg;
#pragma unroll
                for (int n = 0; n < 8; ++n) {
                    const unsigned b0 = kp[(n * 8) * KSTRW];
                    const unsigned b1 = kp[(n * 8) * KSTRW + 4];
                    mma1688(sacc[n], a0, a1, a2, a3, b0, b1);
                }
            }

            const bool needmask = (kb * FKT + 63 > qb * FQT + warp * 16);
            float mt0 = -1e30f, mt1 = -1e30f;
#pragma unroll
            for (int n = 0; n < 8; ++n) {
                float s0 = sacc[n][0] * scale, s1 = sacc[n][1] * scale;
                float s2 = sacc[n][2] * scale, s3 = sacc[n][3] * scale;
                if (needmask) {
                    const int c0 = kb * FKT + n * 8 + 2 * tg;
                    if (c0     > row0) s0 = -1e30f;
                    if (c0 + 1 > row0) s1 = -1e30f;
                    if (c0     > row1) s2 = -1e30f;
                    if (c0 + 1 > row1) s3 = -1e30f;
                }
                sacc[n][0] = s0; sacc[n][1] = s1;
                sacc[n][2] = s2; sacc[n][3] = s3;
                mt0 = fmaxf(mt0, fmaxf(s0, s1));
                mt1 = fmaxf(mt1, fmaxf(s2, s3));
            }
            mt0 = fmaxf(mt0, __shfl_xor_sync(0xffffffffu, mt0, 1));
            mt0 = fmaxf(mt0, __shfl_xor_sync(0xffffffffu, mt0, 2));
            mt1 = fmaxf(mt1, __shfl_xor_sync(0xffffffffu, mt1, 1));
            mt1 = fmaxf(mt1, __shfl_xor_sync(0xffffffffu, mt1, 2));

            const float mn0 = fmaxf(m0, mt0), mn1 = fmaxf(m1, mt1);
            const float cr0 = __expf(m0 - mn0), cr1 = __expf(m1 - mn1);
            float ls0 = 0.f, ls1 = 0.f;
#pragma unroll
            for (int n = 0; n < 8; ++n) {
                sacc[n][0] = __expf(sacc[n][0] - mn0);
                sacc[n][1] = __expf(sacc[n][1] - mn0);
                sacc[n][2] = __expf(sacc[n][2] - mn1);
                sacc[n][3] = __expf(sacc[n][3] - mn1);
                ls0 += sacc[n][0] + sacc[n][1];
                ls1 += sacc[n][2] + sacc[n][3];
            }
            ls0 += __shfl_xor_sync(0xffffffffu, ls0, 1);
            ls0 += __shfl_xor_sync(0xffffffffu, ls0, 2);
            ls1 += __shfl_xor_sync(0xffffffffu, ls1, 1);
            ls1 += __shfl_xor_sync(0xffffffffu, ls1, 2);
            l0 = l0 * cr0 + ls0;
            l1 = l1 * cr1 + ls1;
            m0 = mn0; m1 = mn1;

#pragma unroll
            for (int n = 0; n < 16; ++n) {
                oacc[n][0] *= cr0; oacc[n][1] *= cr0;
                oacc[n][2] *= cr1; oacc[n][3] *= cr1;
            }

#pragma unroll
            for (int ks = 0; ks < 8; ++ks) {
                const float v00 = __shfl_sync(0xffffffffu, sacc[ks][0], srcA);
                const float v01 = __shfl_sync(0xffffffffu, sacc[ks][1], srcA);
                const float v02 = __shfl_sync(0xffffffffu, sacc[ks][2], srcA);
                const float v03 = __shfl_sync(0xffffffffu, sacc[ks][3], srcA);
                const float v10 = __shfl_sync(0xffffffffu, sacc[ks][0], srcB);
                const float v11 = __shfl_sync(0xffffffffu, sacc[ks][1], srcB);
                const float v12 = __shfl_sync(0xffffffffu, sacc[ks][2], srcB);
                const float v13 = __shfl_sync(0xffffffffu, sacc[ks][3], srcB);
                const float pa0 = psel ? v01 : v00;
                const float pa1 = psel ? v03 : v02;
                const float pa2 = psel ? v11 : v10;
                const float pa3 = psel ? v13 : v12;

                unsigned ah[4], al[4];
                ah[0] = f2tf32(pa0); al[0] = f2tf32(pa0 - __uint_as_float(ah[0]));
                ah[1] = f2tf32(pa1); al[1] = f2tf32(pa1 - __uint_as_float(ah[1]));
                ah[2] = f2tf32(pa2); al[2] = f2tf32(pa2 - __uint_as_float(ah[2]));
                ah[3] = f2tf32(pa3); al[3] = f2tf32(pa3 - __uint_as_float(ah[3]));

                const unsigned* vp = Vb + (ks * 8 + tg) * VSTRW + g;
#pragma unroll
                for (int n = 0; n < 16; ++n) {
                    const unsigned b0 = vp[n * 8];
                    const unsigned b1 = vp[n * 8 + 4 * VSTRW];
                    mma1688(oacc[n], ah[0], ah[1], ah[2], ah[3], b0, b1);
                    mma1688(oacc[n], al[0], al[1], al[2], al[3], b0, b1);
                }
            }
        }

        asm volatile("cp.async.wait_group 0;");
        __syncthreads();
        if (kb + 1 < nkt) {
            CVT_TILE(b ^ 1);
            __syncthreads();
        }
    }

    const float inv0 = 1.0f / l0, inv1 = 1.0f / l1;
    float* op0 = ctx + (size_t)row0 * Hdim + h * HDIM;
    float* op1 = op0 + (size_t)8 * Hdim;
#pragma unroll
    for (int n = 0; n < 16; ++n) {
        const int col = n * 8 + 2 * tg;
        float2 w0 = make_float2(oacc[n][0] * inv0, oacc[n][1] * inv0);
        float2 w1 = make_float2(oacc[n][2] * inv1, oacc[n][3] * inv1);
        *reinterpret_cast<float2*>(op0 + col) = w0;
        *reinterpret_cast<float2*>(op1 + col) = w1;
    }
#undef LOAD_TILE
#undef CVT_TILE
}

// ---------------------------------------------------------------------------
// Launch: QKV gemm -> RoPE -> flash attention -> dense gemm
// ---------------------------------------------------------------------------
extern "C" void kernel_launch(void* const* d_in, const int* in_sizes, int n_in,
                              void* d_out, int out_size) {
    const float* hidden  = (const float*)d_in[0];
    const float* W_qkv   = (const float*)d_in[2];
    const float* b_qkv   = (const float*)d_in[3];
    const float* W_dense = (const float*)d_in[4];
    const float* b_dense = (const float*)d_in[5];
    float* out = (float*)d_out;

    float*  qkv = nullptr;
    float*  ctx = nullptr;
    float2* tab = nullptr;
    cudaGetSymbolAddress((void**)&qkv, g_qkv);
    cudaGetSymbolAddress((void**)&ctx, g_ctx);
    cudaGetSymbolAddress((void**)&tab, g_rope);

    cudaFuncSetAttribute(reinterpret_cast<const void*>(gemm_tc3),
                         cudaFuncAttributeMaxDynamicSharedMemorySize, G3SMEM);
    cudaFuncSetAttribute(reinterpret_cast<const void*>(flash_attn_mma),
                         cudaFuncAttributeMaxDynamicSharedMemorySize, FSMEM);

    dim3 g1(QKVN / 128, Sdim / 128);
    gemm_tc3<<<g1, 256, G3SMEM>>>(hidden, W_qkv, b_qkv, qkv, Sdim, QKVN, Hdim);

    rope_table_kernel<<<(Sdim * 16 + 255) / 256, 256>>>(tab);
    rope_apply_kernel<<<(Sdim * NHEAD * 16 + 255) / 256, 256>>>(qkv, tab);

    dim3 g2(Sdim / FQT, NHEAD);
    flash_attn_mma<<<g2, 256, FSMEM>>>(qkv, ctx);

    dim3 g3(Hdim / 128, Sdim / 128);
    gemm_tc3<<<g3, 256, G3SMEM>>>(ctx, W_dense, b_dense, out, Sdim, Hdim, Hdim);
}

// round 13
// speedup vs baseline: 1.9642x; 1.0486x over previous
#include <cuda_runtime.h>
#include <math.h>
#include <stdint.h>

// Problem constants
#define Sdim  2048
#define Hdim  4096
#define NHEAD 32
#define HDIM  128
#define QKVN  12288   // 3*Hdim

// Scratch (allocation-free rule: __device__ globals) — 134 MB, proven to run.
__device__ float  g_qkv[(size_t)Sdim * QKVN];    // ~100.7 MB
__device__ float  g_ctx[(size_t)Sdim * Hdim];    // ~33.6 MB
__device__ float2 g_rope[Sdim * 16];             // cos/sin table

__device__ __forceinline__ unsigned f2tf32(float x) {
    unsigned u;
    asm("cvt.rna.tf32.f32 %0, %1;" : "=r"(u) : "f"(x));
    return u;
}
__device__ __forceinline__ unsigned tf32bits(unsigned fb) {
    unsigned u;
    asm("cvt.rna.tf32.f32 %0, %1;" : "=r"(u) : "f"(__uint_as_float(fb)));
    return u;
}
__device__ __forceinline__ void mma1688(float* c, unsigned a0, unsigned a1,
                                        unsigned a2, unsigned a3,
                                        unsigned b0, unsigned b1) {
    asm volatile(
        "mma.sync.aligned.m16n8k8.row.col.f32.tf32.tf32.f32 "
        "{%0,%1,%2,%3}, {%4,%5,%6,%7}, {%8,%9}, {%0,%1,%2,%3};\n"
        : "+f"(c[0]), "+f"(c[1]), "+f"(c[2]), "+f"(c[3])
        : "r"(a0), "r"(a1), "r"(a2), "r"(a3), "r"(b0), "r"(b1));
}
__device__ __forceinline__ void cp16(unsigned saddr, const void* gptr) {
    asm volatile("cp.async.cg.shared.global [%0], [%1], 16;" ::
                 "r"(saddr), "l"(gptr));
}
__device__ __forceinline__ uint32_t smem_u32(const void* p) {
    uint32_t a;
    asm("{ .reg .u64 t; cvta.to.shared.u64 t, %1; cvt.u32.u64 %0, t; }"
        : "=r"(a) : "l"(p));
    return a;
}

// ---------------------------------------------------------------------------
// TF32 tensor-core GEMM v4:  C[M,N] = A[M,K] @ B[N,K]^T + bias[N]
// fp32 inputs. CTA tile 128(M)x256(N), BK=32, warp tile 64x64 (2x4 warps).
// cp.async 3-stage ring of RAW fp32 -> ldmatrix.x4 -> cvt-in-regs -> mma.
// Crossbar bytes/MAC: 0.125 frag + 0.047 staging (v3 was ~0.52).
// smem row stride 144B. 166 KB smem, 1 CTA/SM.
// ---------------------------------------------------------------------------
#define GST_B 144                     // smem row stride bytes
#define ABUF  (128 * GST_B)           // A tile buffer: 18432 B
#define BBUF  (256 * GST_B)           // B tile buffer: 36864 B
#define STAGE (ABUF + BBUF)           // 55296 B
#define G4SMEM (3 * STAGE)            // 165888 B

__global__ __launch_bounds__(256, 1) void gemm_tc4(
    const float* __restrict__ A, const float* __restrict__ B,
    const float* __restrict__ bias, float* __restrict__ C,
    int M, int N, int K)
{
    extern __shared__ unsigned char gsm[];
    const uint32_t sb = smem_u32(gsm);

    const int tid  = threadIdx.x;
    const int warp = tid >> 5;
    const int lane = tid & 31;
    const int wm = warp >> 2;         // 0..1  (M, x64)
    const int wn = warp & 3;          // 0..3  (N, x64)
    const int g  = lane >> 2;
    const int tg = lane & 3;
    const int bm = blockIdx.y * 128;
    const int bn = blockIdx.x * 256;

    // cp.async mapping: thread -> rows (tid>>3 + 32*i), chunk (tid&7)
    const int lrow = tid >> 3;        // 0..31
    const int lc   = tid & 7;         // 0..7
    const float* agp = A + (size_t)(bm + lrow) * K + lc * 4;
    const float* bgp = B + (size_t)(bn + lrow) * K + lc * 4;
    const uint32_t sOff = (uint32_t)lrow * GST_B + lc * 16;

    const int nIter = K >> 5;         // K/32

#define ISSUE(itx)                                                             \
    {                                                                          \
        const uint32_t _st = sb + ((itx) % 3) * STAGE;                         \
        const int _k0 = (itx) * 32;                                            \
        _Pragma("unroll")                                                      \
        for (int i = 0; i < 4; ++i)                                            \
            cp16(_st + sOff + i * (32 * GST_B),                                \
                 agp + (size_t)(32 * i) * K + _k0);                            \
        _Pragma("unroll")                                                      \
        for (int i = 0; i < 8; ++i)                                            \
            cp16(_st + ABUF + sOff + i * (32 * GST_B),                         \
                 bgp + (size_t)(32 * i) * K + _k0);                            \
        asm volatile("cp.async.commit_group;");                                \
    }

    ISSUE(0);
    ISSUE(1);

    float acc[4][8][4];
#pragma unroll
    for (int i = 0; i < 4; ++i)
#pragma unroll
        for (int j = 0; j < 8; ++j)
#pragma unroll
            for (int c = 0; c < 4; ++c) acc[i][j][c] = 0.f;

    // ldmatrix per-thread byte offsets (v3-verified mapping, wn*64 for v4).
    const uint32_t aOff =
        (uint32_t)(wm * 64 + ((lane >> 3) & 1) * 8 + (lane & 7)) * GST_B +
        (lane >> 4) * 16;
    const uint32_t bOff =
        (uint32_t)(wn * 64 + ((lane >> 4) & 1) * 8 + (lane & 7)) * GST_B +
        ((lane >> 3) & 1) * 16;

    for (int it = 0; it < nIter; ++it) {
        if (it + 1 == nIter)
            asm volatile("cp.async.wait_group 0;" ::: "memory");
        else
            asm volatile("cp.async.wait_group 1;" ::: "memory");
        __syncthreads();                     // buf(it) ready; old reads done
        if (it + 2 < nIter) ISSUE(it + 2);   // overwrites buf(it-1): safe

        const uint32_t ab = sb + (it % 3) * STAGE;
        const uint32_t bb = ab + ABUF;

#pragma unroll
        for (int ks = 0; ks < 4; ++ks) {
            unsigned af[4][4], bf[8][2];
#pragma unroll
            for (int i = 0; i < 4; ++i) {
                asm volatile(
                    "ldmatrix.sync.aligned.m8n8.x4.shared.b16 "
                    "{%0,%1,%2,%3}, [%4];"
                    : "=r"(af[i][0]), "=r"(af[i][1]),
                      "=r"(af[i][2]), "=r"(af[i][3])
                    : "r"(ab + aOff + i * (16 * GST_B) + ks * 32));
            }
#pragma unroll
            for (int jp = 0; jp < 4; ++jp) {
                asm volatile(
                    "ldmatrix.sync.aligned.m8n8.x4.shared.b16 "
                    "{%0,%1,%2,%3}, [%4];"
                    : "=r"(bf[2 * jp][0]), "=r"(bf[2 * jp][1]),
                      "=r"(bf[2 * jp + 1][0]), "=r"(bf[2 * jp + 1][1])
                    : "r"(bb + bOff + jp * (16 * GST_B) + ks * 32));
            }
            // fp32 -> tf32 in registers (no extra crossbar traffic)
#pragma unroll
            for (int i = 0; i < 4; ++i) {
                af[i][0] = tf32bits(af[i][0]); af[i][1] = tf32bits(af[i][1]);
                af[i][2] = tf32bits(af[i][2]); af[i][3] = tf32bits(af[i][3]);
            }
#pragma unroll
            for (int j = 0; j < 8; ++j) {
                bf[j][0] = tf32bits(bf[j][0]); bf[j][1] = tf32bits(bf[j][1]);
            }
#pragma unroll
            for (int i = 0; i < 4; ++i)
#pragma unroll
                for (int j = 0; j < 8; ++j)
                    mma1688(acc[i][j], af[i][0], af[i][1], af[i][2], af[i][3],
                            bf[j][0], bf[j][1]);
        }
    }
#undef ISSUE

    // Epilogue: c0:(g,2tg) c1:(g,2tg+1) c2:(g+8,2tg) c3:(g+8,2tg+1)
#pragma unroll
    for (int i = 0; i < 4; ++i) {
        const int row = bm + wm * 64 + i * 16 + g;
#pragma unroll
        for (int j = 0; j < 8; ++j) {
            const int col = bn + wn * 64 + j * 8 + tg * 2;
            const float b0 = bias[col], b1 = bias[col + 1];
            C[(size_t)row * N + col]           = acc[i][j][0] + b0;
            C[(size_t)row * N + col + 1]       = acc[i][j][1] + b1;
            C[(size_t)(row + 8) * N + col]     = acc[i][j][2] + b0;
            C[(size_t)(row + 8) * N + col + 1] = acc[i][j][3] + b1;
        }
    }
}

// ---------------------------------------------------------------------------
// RoPE: precompute cos/sin table (double precision, once), then fp32 apply.
// ---------------------------------------------------------------------------
__global__ void rope_table_kernel(float2* __restrict__ tab) {
    const int idx = blockIdx.x * blockDim.x + threadIdx.x;
    if (idx >= Sdim * 16) return;
    const int i = idx & 15;
    const int s = idx >> 4;
    const double invf = pow(10000.0, -((double)i / 16.0));
    double sd, cd;
    sincos((double)s * invf, &sd, &cd);
    tab[idx] = make_float2((float)cd, (float)sd);
}

__global__ void rope_apply_kernel(float* __restrict__ qkv,
                                  const float2* __restrict__ tab) {
    const int idx = blockIdx.x * blockDim.x + threadIdx.x;
    if (idx >= Sdim * NHEAD * 16) return;
    const int i = idx & 15;
    const int h = (idx >> 4) & 31;
    const int s = idx >> 9;
    const float2 cs = tab[s * 16 + i];
    const float c = cs.x, sn = cs.y;

    float* base = qkv + (size_t)s * QKVN + h * 384;
    {   // q
        const float x0 = base[i], x1 = base[i + 16];
        base[i]      = x0 * c - x1 * sn;
        base[i + 16] = x1 * c + x0 * sn;
    }
    {   // k
        const float x0 = base[128 + i], x1 = base[128 + i + 16];
        base[128 + i]      = x0 * c - x1 * sn;
        base[128 + i + 16] = x1 * c + x0 * sn;
    }
}

// ---------------------------------------------------------------------------
// MMA-based causal flash attention (tf32).  (unchanged, measured ~448us)
// ---------------------------------------------------------------------------
#define FQT   128
#define FKT   64
#define QSTRW 132
#define KSTRW 132
#define VSTRW 136
#define FSMEM ((FQT*QSTRW + 2*FKT*KSTRW + 2*FKT*VSTRW) * 4)  // 204800 B

__global__ __launch_bounds__(256, 1) void flash_attn_mma(
    const float* __restrict__ qkv, float* __restrict__ ctx)
{
    extern __shared__ unsigned sh[];
    unsigned* Qs = sh;
    unsigned* Ks = sh + FQT * QSTRW;
    unsigned* Vs = Ks + 2 * FKT * KSTRW;

    const unsigned shbase  = smem_u32(sh);
    const unsigned ks_base = shbase + FQT * QSTRW * 4;
    const unsigned vs_base = ks_base + 2 * FKT * KSTRW * 4;

    const int h    = blockIdx.y;
    const int qb   = (gridDim.x - 1) - blockIdx.x;
    const int tid  = threadIdx.x;
    const int warp = tid >> 5;
    const int lane = tid & 31;
    const int g    = lane >> 2;
    const int tg   = lane & 3;
    const int srcA = (lane & 28) + (tg >> 1);
    const int srcB = srcA + 2;
    const int psel = tg & 1;

    const float* qbase = qkv + (size_t)(qb * FQT) * QKVN + h * 384;

#pragma unroll
    for (int i = 0; i < 16; ++i) {
        const int idx = tid + 256 * i;
        const int row = idx >> 5, c4 = idx & 31;
        float4 v = *reinterpret_cast<const float4*>(
            qbase + (size_t)row * QKVN + c4 * 4);
        unsigned* p = Qs + row * QSTRW + c4 * 4;
        p[0] = f2tf32(v.x); p[1] = f2tf32(v.y);
        p[2] = f2tf32(v.z); p[3] = f2tf32(v.w);
    }

    const int nkt = 2 * (qb + 1);

#define LOAD_TILE(buf, kb)                                                      \
    {                                                                           \
        const float* kb_g = qkv + (size_t)((kb) * FKT) * QKVN + h * 384 + 128;  \
        const unsigned ksd = ks_base + (buf) * (FKT * KSTRW * 4);               \
        const unsigned vsd = vs_base + (buf) * (FKT * VSTRW * 4);               \
        _Pragma("unroll")                                                       \
        for (int i = 0; i < 8; ++i) {                                           \
            const int idx = tid + 256 * i;                                      \
            const int row = idx >> 5, c = idx & 31;                             \
            cp16(ksd + row * (KSTRW * 4) + c * 16,                              \
                 kb_g + (size_t)row * QKVN + c * 4);                            \
            cp16(vsd + row * (VSTRW * 4) + c * 16,                              \
                 kb_g + 128 + (size_t)row * QKVN + c * 4);                      \
        }                                                                       \
        asm volatile("cp.async.commit_group;");                                 \
    }
#define CVT_TILE(buf)                                                           \
    {                                                                           \
        uint4* kp = reinterpret_cast<uint4*>(Ks + (buf) * FKT * KSTRW);         \
        uint4* vp = reinterpret_cast<uint4*>(Vs + (buf) * FKT * VSTRW);         \
        _Pragma("unroll")                                                       \
        for (int i = 0; i < 9; ++i) {                                           \
            const int idx = tid + 256 * i;                                      \
            if (idx < (FKT * KSTRW) / 4) {                                      \
                uint4 v = kp[idx];                                              \
                v.x = tf32bits(v.x); v.y = tf32bits(v.y);                       \
                v.z = tf32bits(v.z); v.w = tf32bits(v.w);                       \
                kp[idx] = v;                                                    \
            }                                                                   \
            if (idx < (FKT * VSTRW) / 4) {                                      \
                uint4 v = vp[idx];                                              \
                v.x = tf32bits(v.x); v.y = tf32bits(v.y);                       \
                v.z = tf32bits(v.z); v.w = tf32bits(v.w);                       \
                vp[idx] = v;                                                    \
            }                                                                   \
        }                                                                       \
    }

    LOAD_TILE(0, 0);
    asm volatile("cp.async.wait_group 0;");
    __syncthreads();
    CVT_TILE(0);
    __syncthreads();

    float oacc[16][4];
#pragma unroll
    for (int n = 0; n < 16; ++n)
#pragma unroll
        for (int c = 0; c < 4; ++c) oacc[n][c] = 0.f;

    float m0 = -1e30f, m1 = -1e30f, l0 = 0.f, l1 = 0.f;
    const float scale = 0.08838834764831845f;
    const int row0 = qb * FQT + warp * 16 + g;
    const int row1 = row0 + 8;

    for (int kb = 0; kb < nkt; ++kb) {
        const int b = kb & 1;
        if (kb + 1 < nkt) LOAD_TILE(b ^ 1, kb + 1);

        const unsigned* Kb = Ks + b * FKT * KSTRW;
        const unsigned* Vb = Vs + b * FKT * VSTRW;

        const bool fully_masked = (kb * FKT > qb * FQT + warp * 16 + 15);
        if (!fully_masked) {
            float sacc[8][4];
#pragma unroll
            for (int n = 0; n < 8; ++n)
#pragma unroll
                for (int c = 0; c < 4; ++c) sacc[n][c] = 0.f;

            const unsigned* qa = Qs + (warp * 16 + g) * QSTRW + tg;
#pragma unroll
            for (int ks = 0; ks < 16; ++ks) {
                const unsigned a0 = qa[ks * 8];
                const unsigned a1 = qa[ks * 8 + 8 * QSTRW];
                const unsigned a2 = qa[ks * 8 + 4];
                const unsigned a3 = qa[ks * 8 + 4 + 8 * QSTRW];
                const unsigned* kp = Kb + g * KSTRW + ks * 8 + tg;
#pragma unroll
                for (int n = 0; n < 8; ++n) {
                    const unsigned b0 = kp[(n * 8) * KSTRW];
                    const unsigned b1 = kp[(n * 8) * KSTRW + 4];
                    mma1688(sacc[n], a0, a1, a2, a3, b0, b1);
                }
            }

            const bool needmask = (kb * FKT + 63 > qb * FQT + warp * 16);
            float mt0 = -1e30f, mt1 = -1e30f;
#pragma unroll
            for (int n = 0; n < 8; ++n) {
                float s0 = sacc[n][0] * scale, s1 = sacc[n][1] * scale;
                float s2 = sacc[n][2] * scale, s3 = sacc[n][3] * scale;
                if (needmask) {
                    const int c0 = kb * FKT + n * 8 + 2 * tg;
                    if (c0     > row0) s0 = -1e30f;
                    if (c0 + 1 > row0) s1 = -1e30f;
                    if (c0     > row1) s2 = -1e30f;
                    if (c0 + 1 > row1) s3 = -1e30f;
                }
                sacc[n][0] = s0; sacc[n][1] = s1;
                sacc[n][2] = s2; sacc[n][3] = s3;
                mt0 = fmaxf(mt0, fmaxf(s0, s1));
                mt1 = fmaxf(mt1, fmaxf(s2, s3));
            }
            mt0 = fmaxf(mt0, __shfl_xor_sync(0xffffffffu, mt0, 1));
            mt0 = fmaxf(mt0, __shfl_xor_sync(0xffffffffu, mt0, 2));
            mt1 = fmaxf(mt1, __shfl_xor_sync(0xffffffffu, mt1, 1));
            mt1 = fmaxf(mt1, __shfl_xor_sync(0xffffffffu, mt1, 2));

            const float mn0 = fmaxf(m0, mt0), mn1 = fmaxf(m1, mt1);
            const float cr0 = __expf(m0 - mn0), cr1 = __expf(m1 - mn1);
            float ls0 = 0.f, ls1 = 0.f;
#pragma unroll
            for (int n = 0; n < 8; ++n) {
                sacc[n][0] = __expf(sacc[n][0] - mn0);
                sacc[n][1] = __expf(sacc[n][1] - mn0);
                sacc[n][2] = __expf(sacc[n][2] - mn1);
                sacc[n][3] = __expf(sacc[n][3] - mn1);
                ls0 += sacc[n][0] + sacc[n][1];
                ls1 += sacc[n][2] + sacc[n][3];
            }
            ls0 += __shfl_xor_sync(0xffffffffu, ls0, 1);
            ls0 += __shfl_xor_sync(0xffffffffu, ls0, 2);
            ls1 += __shfl_xor_sync(0xffffffffu, ls1, 1);
            ls1 += __shfl_xor_sync(0xffffffffu, ls1, 2);
            l0 = l0 * cr0 + ls0;
            l1 = l1 * cr1 + ls1;
            m0 = mn0; m1 = mn1;

#pragma unroll
            for (int n = 0; n < 16; ++n) {
                oacc[n][0] *= cr0; oacc[n][1] *= cr0;
                oacc[n][2] *= cr1; oacc[n][3] *= cr1;
            }

#pragma unroll
            for (int ks = 0; ks < 8; ++ks) {
                const float v00 = __shfl_sync(0xffffffffu, sacc[ks][0], srcA);
                const float v01 = __shfl_sync(0xffffffffu, sacc[ks][1], srcA);
                const float v02 = __shfl_sync(0xffffffffu, sacc[ks][2], srcA);
                const float v03 = __shfl_sync(0xffffffffu, sacc[ks][3], srcA);
                const float v10 = __shfl_sync(0xffffffffu, sacc[ks][0], srcB);
                const float v11 = __shfl_sync(0xffffffffu, sacc[ks][1], srcB);
                const float v12 = __shfl_sync(0xffffffffu, sacc[ks][2], srcB);
                const float v13 = __shfl_sync(0xffffffffu, sacc[ks][3], srcB);
                const float pa0 = psel ? v01 : v00;
                const float pa1 = psel ? v03 : v02;
                const float pa2 = psel ? v11 : v10;
                const float pa3 = psel ? v13 : v12;

                unsigned ah[4], al[4];
                ah[0] = f2tf32(pa0); al[0] = f2tf32(pa0 - __uint_as_float(ah[0]));
                ah[1] = f2tf32(pa1); al[1] = f2tf32(pa1 - __uint_as_float(ah[1]));
                ah[2] = f2tf32(pa2); al[2] = f2tf32(pa2 - __uint_as_float(ah[2]));
                ah[3] = f2tf32(pa3); al[3] = f2tf32(pa3 - __uint_as_float(ah[3]));

                const unsigned* vp = Vb + (ks * 8 + tg) * VSTRW + g;
#pragma unroll
                for (int n = 0; n < 16; ++n) {
                    const unsigned b0 = vp[n * 8];
                    const unsigned b1 = vp[n * 8 + 4 * VSTRW];
                    mma1688(oacc[n], ah[0], ah[1], ah[2], ah[3], b0, b1);
                    mma1688(oacc[n], al[0], al[1], al[2], al[3], b0, b1);
                }
            }
        }

        asm volatile("cp.async.wait_group 0;");
        __syncthreads();
        if (kb + 1 < nkt) {
            CVT_TILE(b ^ 1);
            __syncthreads();
        }
    }

    const float inv0 = 1.0f / l0, inv1 = 1.0f / l1;
    float* op0 = ctx + (size_t)row0 * Hdim + h * HDIM;
    float* op1 = op0 + (size_t)8 * Hdim;
#pragma unroll
    for (int n = 0; n < 16; ++n) {
        const int col = n * 8 + 2 * tg;
        float2 w0 = make_float2(oacc[n][0] * inv0, oacc[n][1] * inv0);
        float2 w1 = make_float2(oacc[n][2] * inv1, oacc[n][3] * inv1);
        *reinterpret_cast<float2*>(op0 + col) = w0;
        *reinterpret_cast<float2*>(op1 + col) = w1;
    }
#undef LOAD_TILE
#undef CVT_TILE
}

// ---------------------------------------------------------------------------
// Launch: QKV gemm -> RoPE -> flash attention -> dense gemm
// ---------------------------------------------------------------------------
extern "C" void kernel_launch(void* const* d_in, const int* in_sizes, int n_in,
                              void* d_out, int out_size) {
    const float* hidden  = (const float*)d_in[0];
    const float* W_qkv   = (const float*)d_in[2];
    const float* b_qkv   = (const float*)d_in[3];
    const float* W_dense = (const float*)d_in[4];
    const float* b_dense = (const float*)d_in[5];
    float* out = (float*)d_out;

    float*  qkv = nullptr;
    float*  ctx = nullptr;
    float2* tab = nullptr;
    cudaGetSymbolAddress((void**)&qkv, g_qkv);
    cudaGetSymbolAddress((void**)&ctx, g_ctx);
    cudaGetSymbolAddress((void**)&tab, g_rope);

    cudaFuncSetAttribute(reinterpret_cast<const void*>(gemm_tc4),
                         cudaFuncAttributeMaxDynamicSharedMemorySize, G4SMEM);
    cudaFuncSetAttribute(reinterpret_cast<const void*>(flash_attn_mma),
                         cudaFuncAttributeMaxDynamicSharedMemorySize, FSMEM);

    dim3 g1(QKVN / 256, Sdim / 128);
    gemm_tc4<<<g1, 256, G4SMEM>>>(hidden, W_qkv, b_qkv, qkv, Sdim, QKVN, Hdim);

    rope_table_kernel<<<(Sdim * 16 + 255) / 256, 256>>>(tab);
    rope_apply_kernel<<<(Sdim * NHEAD * 16 + 255) / 256, 256>>>(qkv, tab);

    dim3 g2(Sdim / FQT, NHEAD);
    flash_attn_mma<<<g2, 256, FSMEM>>>(qkv, ctx);

    dim3 g3(Hdim / 256, Sdim / 128);
    gemm_tc4<<<g3, 256, G4SMEM>>>(ctx, W_dense, b_dense, out, Sdim, Hdim, Hdim);
}

// round 15
// speedup vs baseline: 2.0346x; 1.0358x over previous
#include <cuda_runtime.h>
#include <math.h>
#include <stdint.h>

// Problem constants
#define Sdim  2048
#define Hdim  4096
#define NHEAD 32
#define HDIM  128
#define QKVN  12288   // 3*Hdim

// Scratch (allocation-free rule: __device__ globals) — ~201 MB total.
__device__ float  g_qkv[(size_t)Sdim * QKVN];    // ~100.7 MB (qkv activations)
__device__ float  g_ctx[(size_t)Sdim * Hdim];    // ~33.6 MB (tf32 hidden, then ctx)
__device__ float  g_wt [(size_t)Hdim * Hdim];    // ~67 MB  (tf32 weight chunk)
__device__ float2 g_rope[Sdim * 16];             // cos/sin table

__device__ __forceinline__ unsigned f2tf32(float x) {
    unsigned u;
    asm("cvt.rna.tf32.f32 %0, %1;" : "=r"(u) : "f"(x));
    return u;
}
__device__ __forceinline__ unsigned tf32bits(unsigned fb) {
    unsigned u;
    asm("cvt.rna.tf32.f32 %0, %1;" : "=r"(u) : "f"(__uint_as_float(fb)));
    return u;
}
__device__ __forceinline__ void mma1688(float* c, unsigned a0, unsigned a1,
                                        unsigned a2, unsigned a3,
                                        unsigned b0, unsigned b1) {
    asm volatile(
        "mma.sync.aligned.m16n8k8.row.col.f32.tf32.tf32.f32 "
        "{%0,%1,%2,%3}, {%4,%5,%6,%7}, {%8,%9}, {%0,%1,%2,%3};\n"
        : "+f"(c[0]), "+f"(c[1]), "+f"(c[2]), "+f"(c[3])
        : "r"(a0), "r"(a1), "r"(a2), "r"(a3), "r"(b0), "r"(b1));
}
__device__ __forceinline__ void cp16(unsigned saddr, const void* gptr) {
    asm volatile("cp.async.cg.shared.global [%0], [%1], 16;" ::
                 "r"(saddr), "l"(gptr));
}
__device__ __forceinline__ uint32_t smem_u32(const void* p) {
    uint32_t a;
    asm("{ .reg .u64 t; cvta.to.shared.u64 t, %1; cvt.u32.u64 %0, t; }"
        : "=r"(a) : "l"(p));
    return a;
}

// ---------------------------------------------------------------------------
// Round-COPY fp32 -> tf32(RNA) bit patterns (inputs untouched).
// ---------------------------------------------------------------------------
__global__ void cvt_copy_kernel(const uint4* __restrict__ in,
                                uint4* __restrict__ out, int n4) {
    int i = blockIdx.x * blockDim.x + threadIdx.x;
    const int stride = gridDim.x * blockDim.x;
    for (; i < n4; i += stride) {
        uint4 v = in[i];
        v.x = tf32bits(v.x); v.y = tf32bits(v.y);
        v.z = tf32bits(v.z); v.w = tf32bits(v.w);
        out[i] = v;
    }
}

// ---------------------------------------------------------------------------
// TF32 tensor-core GEMM v5:  C[M,Nchunk] = A[M,K] @ B[Nchunk,K]^T + bias
// A,B hold tf32-rounded bit patterns. CTA tile 128x256, BK=32, warp 64x64.
// cp.async 3-stage ring -> ldmatrix.x4 -> mma. NO cvt in mainloop.
// C rows use stride ldC (C/bias pointers pre-offset by the caller's chunk).
// ---------------------------------------------------------------------------
#define GST_B 144                     // smem row stride bytes
#define ABUF  (128 * GST_B)           // A tile buffer: 18432 B
#define BBUF  (256 * GST_B)           // B tile buffer: 36864 B
#define STAGE (ABUF + BBUF)           // 55296 B
#define G5SMEM (3 * STAGE)            // 165888 B

__global__ __launch_bounds__(256, 1) void gemm_tc5(
    const float* __restrict__ A, const float* __restrict__ B,
    const float* __restrict__ bias, float* __restrict__ C,
    int M, int N, int K, int ldC)
{
    extern __shared__ unsigned char gsm[];
    const uint32_t sb = smem_u32(gsm);

    const int tid  = threadIdx.x;
    const int warp = tid >> 5;
    const int lane = tid & 31;
    const int wm = warp >> 2;         // 0..1  (M, x64)
    const int wn = warp & 3;          // 0..3  (N, x64)
    const int g  = lane >> 2;
    const int tg = lane & 3;
    const int bm = blockIdx.y * 128;
    const int bn = blockIdx.x * 256;

    const int lrow = tid >> 3;        // 0..31
    const int lc   = tid & 7;         // 0..7
    const float* agp = A + (size_t)(bm + lrow) * K + lc * 4;
    const float* bgp = B + (size_t)(bn + lrow) * K + lc * 4;
    const uint32_t sOff = (uint32_t)lrow * GST_B + lc * 16;

    const int nIter = K >> 5;         // K/32

#define ISSUE(itx)                                                             \
    {                                                                          \
        const uint32_t _st = sb + ((itx) % 3) * STAGE;                         \
        const int _k0 = (itx) * 32;                                            \
        _Pragma("unroll")                                                      \
        for (int i = 0; i < 4; ++i)                                            \
            cp16(_st + sOff + i * (32 * GST_B),                                \
                 agp + (size_t)(32 * i) * K + _k0);                            \
        _Pragma("unroll")                                                      \
        for (int i = 0; i < 8; ++i)                                            \
            cp16(_st + ABUF + sOff + i * (32 * GST_B),                         \
                 bgp + (size_t)(32 * i) * K + _k0);                            \
        asm volatile("cp.async.commit_group;");                                \
    }

    ISSUE(0);
    ISSUE(1);

    float acc[4][8][4];
#pragma unroll
    for (int i = 0; i < 4; ++i)
#pragma unroll
        for (int j = 0; j < 8; ++j)
#pragma unroll
            for (int c = 0; c < 4; ++c) acc[i][j][c] = 0.f;

    const uint32_t aOff =
        (uint32_t)(wm * 64 + ((lane >> 3) & 1) * 8 + (lane & 7)) * GST_B +
        (lane >> 4) * 16;
    const uint32_t bOff =
        (uint32_t)(wn * 64 + ((lane >> 4) & 1) * 8 + (lane & 7)) * GST_B +
        ((lane >> 3) & 1) * 16;

    for (int it = 0; it < nIter; ++it) {
        if (it + 1 == nIter)
            asm volatile("cp.async.wait_group 0;" ::: "memory");
        else
            asm volatile("cp.async.wait_group 1;" ::: "memory");
        __syncthreads();                     // buf(it) ready; old reads done
        if (it + 2 < nIter) ISSUE(it + 2);   // overwrites buf(it-1): safe

        const uint32_t ab = sb + (it % 3) * STAGE;
        const uint32_t bb = ab + ABUF;

#pragma unroll
        for (int ks = 0; ks < 4; ++ks) {
            unsigned af[4][4], bf[8][2];
#pragma unroll
            for (int i = 0; i < 4; ++i) {
                asm volatile(
                    "ldmatrix.sync.aligned.m8n8.x4.shared.b16 "
                    "{%0,%1,%2,%3}, [%4];"
                    : "=r"(af[i][0]), "=r"(af[i][1]),
                      "=r"(af[i][2]), "=r"(af[i][3])
                    : "r"(ab + aOff + i * (16 * GST_B) + ks * 32));
            }
#pragma unroll
            for (int jp = 0; jp < 4; ++jp) {
                asm volatile(
                    "ldmatrix.sync.aligned.m8n8.x4.shared.b16 "
                    "{%0,%1,%2,%3}, [%4];"
                    : "=r"(bf[2 * jp][0]), "=r"(bf[2 * jp][1]),
                      "=r"(bf[2 * jp + 1][0]), "=r"(bf[2 * jp + 1][1])
                    : "r"(bb + bOff + jp * (16 * GST_B) + ks * 32));
            }
#pragma unroll
            for (int i = 0; i < 4; ++i)
#pragma unroll
                for (int j = 0; j < 8; ++j)
                    mma1688(acc[i][j], af[i][0], af[i][1], af[i][2], af[i][3],
                            bf[j][0], bf[j][1]);
        }
    }
#undef ISSUE

    // Epilogue: c0:(g,2tg) c1:(g,2tg+1) c2:(g+8,2tg) c3:(g+8,2tg+1)
#pragma unroll
    for (int i = 0; i < 4; ++i) {
        const int row = bm + wm * 64 + i * 16 + g;
#pragma unroll
        for (int j = 0; j < 8; ++j) {
            const int col = bn + wn * 64 + j * 8 + tg * 2;
            const float b0 = bias[col], b1 = bias[col + 1];
            C[(size_t)row * ldC + col]           = acc[i][j][0] + b0;
            C[(size_t)row * ldC + col + 1]       = acc[i][j][1] + b1;
            C[(size_t)(row + 8) * ldC + col]     = acc[i][j][2] + b0;
            C[(size_t)(row + 8) * ldC + col + 1] = acc[i][j][3] + b1;
        }
    }
}

// ---------------------------------------------------------------------------
// RoPE: precompute cos/sin table (double precision, once), then fp32 apply.
// ---------------------------------------------------------------------------
__global__ void rope_table_kernel(float2* __restrict__ tab) {
    const int idx = blockIdx.x * blockDim.x + threadIdx.x;
    if (idx >= Sdim * 16) return;
    const int i = idx & 15;
    const int s = idx >> 4;
    const double invf = pow(10000.0, -((double)i / 16.0));
    double sd, cd;
    sincos((double)s * invf, &sd, &cd);
    tab[idx] = make_float2((float)cd, (float)sd);
}

__global__ void rope_apply_kernel(float* __restrict__ qkv,
                                  const float2* __restrict__ tab) {
    const int idx = blockIdx.x * blockDim.x + threadIdx.x;
    if (idx >= Sdim * NHEAD * 16) return;
    const int i = idx & 15;
    const int h = (idx >> 4) & 31;
    const int s = idx >> 9;
    const float2 cs = tab[s * 16 + i];
    const float c = cs.x, sn = cs.y;

    float* base = qkv + (size_t)s * QKVN + h * 384;
    {   // q
        const float x0 = base[i], x1 = base[i + 16];
        base[i]      = x0 * c - x1 * sn;
        base[i + 16] = x1 * c + x0 * sn;
    }
    {   // k
        const float x0 = base[128 + i], x1 = base[128 + i + 16];
        base[128 + i]      = x0 * c - x1 * sn;
        base[128 + i + 16] = x1 * c + x0 * sn;
    }
}

// ---------------------------------------------------------------------------
// MMA-based causal flash attention (tf32). Epilogue stores ctx pre-rounded
// to tf32 so the dense GEMM needs no cvt (identical bits to prior rounds).
// ---------------------------------------------------------------------------
#define FQT   128
#define FKT   64
#define QSTRW 132
#define KSTRW 132
#define VSTRW 136
#define FSMEM ((FQT*QSTRW + 2*FKT*KSTRW + 2*FKT*VSTRW) * 4)  // 204800 B

__global__ __launch_bounds__(256, 1) void flash_attn_mma(
    const float* __restrict__ qkv, float* __restrict__ ctx)
{
    extern __shared__ unsigned sh[];
    unsigned* Qs = sh;
    unsigned* Ks = sh + FQT * QSTRW;
    unsigned* Vs = Ks + 2 * FKT * KSTRW;

    const unsigned shbase  = smem_u32(sh);
    const unsigned ks_base = shbase + FQT * QSTRW * 4;
    const unsigned vs_base = ks_base + 2 * FKT * KSTRW * 4;

    const int h    = blockIdx.y;
    const int qb   = (gridDim.x - 1) - blockIdx.x;
    const int tid  = threadIdx.x;
    const int warp = tid >> 5;
    const int lane = tid & 31;
    const int g    = lane >> 2;
    const int tg   = lane & 3;
    const int srcA = (lane & 28) + (tg >> 1);
    const int srcB = srcA + 2;
    const int psel = tg & 1;

    const float* qbase = qkv + (size_t)(qb * FQT) * QKVN + h * 384;

#pragma unroll
    for (int i = 0; i < 16; ++i) {
        const int idx = tid + 256 * i;
        const int row = idx >> 5, c4 = idx & 31;
        float4 v = *reinterpret_cast<const float4*>(
            qbase + (size_t)row * QKVN + c4 * 4);
        unsigned* p = Qs + row * QSTRW + c4 * 4;
        p[0] = f2tf32(v.x); p[1] = f2tf32(v.y);
        p[2] = f2tf32(v.z); p[3] = f2tf32(v.w);
    }

    const int nkt = 2 * (qb + 1);

#define LOAD_TILE(buf, kb)                                                      \
    {                                                                           \
        const float* kb_g = qkv + (size_t)((kb) * FKT) * QKVN + h * 384 + 128;  \
        const unsigned ksd = ks_base + (buf) * (FKT * KSTRW * 4);               \
        const unsigned vsd = vs_base + (buf) * (FKT * VSTRW * 4);               \
        _Pragma("unroll")                                                       \
        for (int i = 0; i < 8; ++i) {                                           \
            const int idx = tid + 256 * i;                                      \
            const int row = idx >> 5, c = idx & 31;                             \
            cp16(ksd + row * (KSTRW * 4) + c * 16,                              \
                 kb_g + (size_t)row * QKVN + c * 4);                            \
            cp16(vsd + row * (VSTRW * 4) + c * 16,                              \
                 kb_g + 128 + (size_t)row * QKVN + c * 4);                      \
        }                                                                       \
        asm volatile("cp.async.commit_group;");                                 \
    }
#define CVT_TILE(buf)                                                           \
    {                                                                           \
        uint4* kp = reinterpret_cast<uint4*>(Ks + (buf) * FKT * KSTRW);         \
        uint4* vp = reinterpret_cast<uint4*>(Vs + (buf) * FKT * VSTRW);         \
        _Pragma("unroll")                                                       \
        for (int i = 0; i < 9; ++i) {                                           \
            const int idx = tid + 256 * i;                                      \
            if (idx < (FKT * KSTRW) / 4) {                                      \
                uint4 v = kp[idx];                                              \
                v.x = tf32bits(v.x); v.y = tf32bits(v.y);                       \
                v.z = tf32bits(v.z); v.w = tf32bits(v.w);                       \
                kp[idx] = v;                                                    \
            }                                                                   \
            if (idx < (FKT * VSTRW) / 4) {                                      \
                uint4 v = vp[idx];                                              \
                v.x = tf32bits(v.x); v.y = tf32bits(v.y);                       \
                v.z = tf32bits(v.z); v.w = tf32bits(v.w);                       \
                vp[idx] = v;                                                    \
            }                                                                   \
        }                                                                       \
    }

    LOAD_TILE(0, 0);
    asm volatile("cp.async.wait_group 0;");
    __syncthreads();
    CVT_TILE(0);
    __syncthreads();

    float oacc[16][4];
#pragma unroll
    for (int n = 0; n < 16; ++n)
#pragma unroll
        for (int c = 0; c < 4; ++c) oacc[n][c] = 0.f;

    float m0 = -1e30f, m1 = -1e30f, l0 = 0.f, l1 = 0.f;
    const float scale = 0.08838834764831845f;
    const int row0 = qb * FQT + warp * 16 + g;
    const int row1 = row0 + 8;

    for (int kb = 0; kb < nkt; ++kb) {
        const int b = kb & 1;
        if (kb + 1 < nkt) LOAD_TILE(b ^ 1, kb + 1);

        const unsigned* Kb = Ks + b * FKT * KSTRW;
        const unsigned* Vb = Vs + b * FKT * VSTRW;

        const bool fully_masked = (kb * FKT > qb * FQT + warp * 16 + 15);
        if (!fully_masked) {
            float sacc[8][4];
#pragma unroll
            for (int n = 0; n < 8; ++n)
#pragma unroll
                for (int c = 0; c < 4; ++c) sacc[n][c] = 0.f;

            const unsigned* qa = Qs + (warp * 16 + g) * QSTRW + tg;
#pragma unroll
            for (int ks = 0; ks < 16; ++ks) {
                const unsigned a0 = qa[ks * 8];
                const unsigned a1 = qa[ks * 8 + 8 * QSTRW];
                const unsigned a2 = qa[ks * 8 + 4];
                const unsigned a3 = qa[ks * 8 + 4 + 8 * QSTRW];
                const unsigned* kp = Kb + g * KSTRW + ks * 8 + tg;
#pragma unroll
                for (int n = 0; n < 8; ++n) {
                    const unsigned b0 = kp[(n * 8) * KSTRW];
                    const unsigned b1 = kp[(n * 8) * KSTRW + 4];
                    mma1688(sacc[n], a0, a1, a2, a3, b0, b1);
                }
            }

            const bool needmask = (kb * FKT + 63 > qb * FQT + warp * 16);
            float mt0 = -1e30f, mt1 = -1e30f;
#pragma unroll
            for (int n = 0; n < 8; ++n) {
                float s0 = sacc[n][0] * scale, s1 = sacc[n][1] * scale;
                float s2 = sacc[n][2] * scale, s3 = sacc[n][3] * scale;
                if (needmask) {
                    const int c0 = kb * FKT + n * 8 + 2 * tg;
                    if (c0     > row0) s0 = -1e30f;
                    if (c0 + 1 > row0) s1 = -1e30f;
                    if (c0     > row1) s2 = -1e30f;
                    if (c0 + 1 > row1) s3 = -1e30f;
                }
                sacc[n][0] = s0; sacc[n][1] = s1;
                sacc[n][2] = s2; sacc[n][3] = s3;
                mt0 = fmaxf(mt0, fmaxf(s0, s1));
                mt1 = fmaxf(mt1, fmaxf(s2, s3));
            }
            mt0 = fmaxf(mt0, __shfl_xor_sync(0xffffffffu, mt0, 1));
            mt0 = fmaxf(mt0, __shfl_xor_sync(0xffffffffu, mt0, 2));
            mt1 = fmaxf(mt1, __shfl_xor_sync(0xffffffffu, mt1, 1));
            mt1 = fmaxf(mt1, __shfl_xor_sync(0xffffffffu, mt1, 2));

            const float mn0 = fmaxf(m0, mt0), mn1 = fmaxf(m1, mt1);
            const float cr0 = __expf(m0 - mn0), cr1 = __expf(m1 - mn1);
            float ls0 = 0.f, ls1 = 0.f;
#pragma unroll
            for (int n = 0; n < 8; ++n) {
                sacc[n][0] = __expf(sacc[n][0] - mn0);
                sacc[n][1] = __expf(sacc[n][1] - mn0);
                sacc[n][2] = __expf(sacc[n][2] - mn1);
                sacc[n][3] = __expf(sacc[n][3] - mn1);
                ls0 += sacc[n][0] + sacc[n][1];
                ls1 += sacc[n][2] + sacc[n][3];
            }
            ls0 += __shfl_xor_sync(0xffffffffu, ls0, 1);
            ls0 += __shfl_xor_sync(0xffffffffu, ls0, 2);
            ls1 += __shfl_xor_sync(0xffffffffu, ls1, 1);
            ls1 += __shfl_xor_sync(0xffffffffu, ls1, 2);
            l0 = l0 * cr0 + ls0;
            l1 = l1 * cr1 + ls1;
            m0 = mn0; m1 = mn1;

#pragma unroll
            for (int n = 0; n < 16; ++n) {
                oacc[n][0] *= cr0; oacc[n][1] *= cr0;
                oacc[n][2] *= cr1; oacc[n][3] *= cr1;
            }

#pragma unroll
            for (int ks = 0; ks < 8; ++ks) {
                const float v00 = __shfl_sync(0xffffffffu, sacc[ks][0], srcA);
                const float v01 = __shfl_sync(0xffffffffu, sacc[ks][1], srcA);
                const float v02 = __shfl_sync(0xffffffffu, sacc[ks][2], srcA);
                const float v03 = __shfl_sync(0xffffffffu, sacc[ks][3], srcA);
                const float v10 = __shfl_sync(0xffffffffu, sacc[ks][0], srcB);
                const float v11 = __shfl_sync(0xffffffffu, sacc[ks][1], srcB);
                const float v12 = __shfl_sync(0xffffffffu, sacc[ks][2], srcB);
                const float v13 = __shfl_sync(0xffffffffu, sacc[ks][3], srcB);
                const float pa0 = psel ? v01 : v00;
                const float pa1 = psel ? v03 : v02;
                const float pa2 = psel ? v11 : v10;
                const float pa3 = psel ? v13 : v12;

                unsigned ah[4], al[4];
                ah[0] = f2tf32(pa0); al[0] = f2tf32(pa0 - __uint_as_float(ah[0]));
                ah[1] = f2tf32(pa1); al[1] = f2tf32(pa1 - __uint_as_float(ah[1]));
                ah[2] = f2tf32(pa2); al[2] = f2tf32(pa2 - __uint_as_float(ah[2]));
                ah[3] = f2tf32(pa3); al[3] = f2tf32(pa3 - __uint_as_float(ah[3]));

                const unsigned* vp = Vb + (ks * 8 + tg) * VSTRW + g;
#pragma unroll
                for (int n = 0; n < 16; ++n) {
                    const unsigned b0 = vp[n * 8];
                    const unsigned b1 = vp[n * 8 + 4 * VSTRW];
                    mma1688(oacc[n], ah[0], ah[1], ah[2], ah[3], b0, b1);
                    mma1688(oacc[n], al[0], al[1], al[2], al[3], b0, b1);
                }
            }
        }

        asm volatile("cp.async.wait_group 0;");
        __syncthreads();
        if (kb + 1 < nkt) {
            CVT_TILE(b ^ 1);
            __syncthreads();
        }
    }

    // normalize + store ctx pre-rounded to tf32 (dense GEMM needs no cvt)
    const float inv0 = 1.0f / l0, inv1 = 1.0f / l1;
    float* op0 = ctx + (size_t)row0 * Hdim + h * HDIM;
    float* op1 = op0 + (size_t)8 * Hdim;
#pragma unroll
    for (int n = 0; n < 16; ++n) {
        const int col = n * 8 + 2 * tg;
        float2 w0, w1;
        w0.x = __uint_as_float(f2tf32(oacc[n][0] * inv0));
        w0.y = __uint_as_float(f2tf32(oacc[n][1] * inv0));
        w1.x = __uint_as_float(f2tf32(oacc[n][2] * inv1));
        w1.y = __uint_as_float(f2tf32(oacc[n][3] * inv1));
        *reinterpret_cast<float2*>(op0 + col) = w0;
        *reinterpret_cast<float2*>(op1 + col) = w1;
    }
#undef LOAD_TILE
#undef CVT_TILE
}

// ---------------------------------------------------------------------------
// Launch plan (single stream, graph-safe, inputs read-only):
//   cvt hidden -> g_ctx (tf32 A for QKV gemms; g_ctx free until flash)
//   3x { cvt W_qkv chunk -> g_wt ; gemm chunk (zero-cvt) }
//   RoPE ; flash (writes tf32 ctx into g_ctx)
//   cvt W_dense -> g_wt ; dense gemm (zero-cvt)
// ---------------------------------------------------------------------------
extern "C" void kernel_launch(void* const* d_in, const int* in_sizes, int n_in,
                              void* d_out, int out_size) {
    const float* hidden  = (const float*)d_in[0];
    const float* W_qkv   = (const float*)d_in[2];
    const float* b_qkv   = (const float*)d_in[3];
    const float* W_dense = (const float*)d_in[4];
    const float* b_dense = (const float*)d_in[5];
    float* out = (float*)d_out;

    float*  qkv = nullptr;
    float*  ctx = nullptr;
    float*  wt  = nullptr;
    float2* tab = nullptr;
    cudaGetSymbolAddress((void**)&qkv, g_qkv);
    cudaGetSymbolAddress((void**)&ctx, g_ctx);
    cudaGetSymbolAddress((void**)&wt,  g_wt);
    cudaGetSymbolAddress((void**)&tab, g_rope);

    cudaFuncSetAttribute(reinterpret_cast<const void*>(gemm_tc5),
                         cudaFuncAttributeMaxDynamicSharedMemorySize, G5SMEM);
    cudaFuncSetAttribute(reinterpret_cast<const void*>(flash_attn_mma),
                         cudaFuncAttributeMaxDynamicSharedMemorySize, FSMEM);

    const int wchunk4 = Hdim * Hdim / 4;            // 4096x4096 / 4

    // tf32(hidden) -> g_ctx (consumed by the QKV gemms before flash)
    cvt_copy_kernel<<<2048, 256>>>((const uint4*)hidden, (uint4*)ctx,
                                   Sdim * Hdim / 4);

    // QKV gemm in 3 N-chunks of 4096, each with pre-rounded weights in g_wt
    dim3 gq(Hdim / 256, Sdim / 128);                // (16,16)
    for (int c = 0; c < 3; ++c) {
        cvt_copy_kernel<<<2048, 256>>>(
            (const uint4*)(W_qkv + (size_t)c * Hdim * Hdim), (uint4*)wt,
            wchunk4);
        gemm_tc5<<<gq, 256, G5SMEM>>>(ctx, wt, b_qkv + c * Hdim,
                                      qkv + c * Hdim, Sdim, Hdim, Hdim, QKVN);
    }

    rope_table_kernel<<<(Sdim * 16 + 255) / 256, 256>>>(tab);
    rope_apply_kernel<<<(Sdim * NHEAD * 16 + 255) / 256, 256>>>(qkv, tab);

    dim3 g2(Sdim / FQT, NHEAD);
    flash_attn_mma<<<g2, 256, FSMEM>>>(qkv, ctx);   // overwrites g_ctx w/ ctx

    // dense gemm with pre-rounded weights (g_wt free after QKV chunks)
    cvt_copy_kernel<<<2048, 256>>>((const uint4*)W_dense, (uint4*)wt, wchunk4);
    dim3 gd(Hdim / 256, Sdim / 128);
    gemm_tc5<<<gd, 256, G5SMEM>>>(ctx, wt, b_dense, out, Sdim, Hdim, Hdim,
                                  Hdim);
}